// round 14
// baseline (speedup 1.0000x reference)
#include <cuda_runtime.h>
#include <math.h>
#include <stdint.h>

#define N_  768
#define A_  768
#define S_  384
#define P_  128
#define H_  16
#define D_  48
#define NN  (N_*N_)

// ---------------- scratch (no allocations allowed) ----------------
__device__ float d_sn [N_*S_];
__device__ float d_an [N_*A_];
__device__ float d_a2 [N_*A_];
__device__ float d_q  [N_*A_];
__device__ float d_k  [N_*A_];
__device__ float d_v  [N_*A_];
__device__ float d_gt [N_*A_];
__device__ float d_bias[H_*NN];         // [H][N][N]
__device__ float d_o  [N_*A_];
__device__ float d_gate[N_*A_];
__device__ float d_opart[2*N_*A_];      // split-KV unnormalized partials
__device__ float2 d_ml[2*H_*N_];        // (m, l) per split/head/row
__device__ unsigned int d_pbctr;        // pairbias work-stealing counter

// ---------------- helpers ----------------
__device__ __forceinline__ uint32_t f2tf(float f) {
    uint32_t u;
    asm("cvt.rna.tf32.f32 %0, %1;" : "=r"(u) : "f"(f));
    return u;
}
__device__ __forceinline__ void mma_tf32(float* c, const uint32_t* a, const uint32_t* b) {
    asm volatile("mma.sync.aligned.m16n8k8.row.col.f32.tf32.tf32.f32 "
                 "{%0,%1,%2,%3}, {%4,%5,%6,%7}, {%8,%9}, {%0,%1,%2,%3};"
                 : "+f"(c[0]), "+f"(c[1]), "+f"(c[2]), "+f"(c[3])
                 : "r"(a[0]), "r"(a[1]), "r"(a[2]), "r"(a[3]), "r"(b[0]), "r"(b[1]));
}
__device__ __forceinline__ float sigm(float x) { return 1.f / (1.f + __expf(-x)); }

// ---------------- row LayerNorm ----------------
template<int COLS, int RST>
__global__ __launch_bounds__(256) void ln_kernel(const float* __restrict__ x,
                                                 const float* __restrict__ w,
                                                 float* __restrict__ y) {
    if (RST && blockIdx.x == 0 && threadIdx.x == 0)
        d_pbctr = 0;                     // reset stealing counter for fused_mid
    int row = blockIdx.x;
    const float* xr = x + (size_t)row * COLS;
    float s = 0.f, s2 = 0.f;
    for (int c = threadIdx.x; c < COLS; c += blockDim.x) {
        float v = xr[c]; s += v; s2 += v * v;
    }
    __shared__ float red[64];
    #pragma unroll
    for (int o = 16; o; o >>= 1) {
        s  += __shfl_xor_sync(0xffffffffu, s,  o);
        s2 += __shfl_xor_sync(0xffffffffu, s2, o);
    }
    int wid = threadIdx.x >> 5, lid = threadIdx.x & 31;
    if (lid == 0) { red[wid] = s; red[wid + 32] = s2; }
    __syncthreads();
    if (wid == 0) {
        s  = (lid < 8) ? red[lid]      : 0.f;
        s2 = (lid < 8) ? red[lid + 32] : 0.f;
        #pragma unroll
        for (int o = 4; o; o >>= 1) {
            s  += __shfl_xor_sync(0xffffffffu, s,  o);
            s2 += __shfl_xor_sync(0xffffffffu, s2, o);
        }
        if (lid == 0) { red[0] = s; red[1] = s2; }
    }
    __syncthreads();
    float mean = red[0] / COLS;
    float var  = red[1] / COLS - mean * mean;
    float rs   = rsqrtf(var + 1e-5f);
    float* yr = y + (size_t)row * COLS;
    for (int c = threadIdx.x; c < COLS; c += blockDim.x) {
        float v = (xr[c] - mean) * rs;
        if (w) v *= w[c];
        yr[c] = v;
    }
}

// ---------------- generic tf32 GEMM (standalone, for out-proj) ----------------
template<int EPI>
__global__ __launch_bounds__(256) void gemm_tf32(const float* __restrict__ A,
                                                 const float* __restrict__ B,
                                                 float* __restrict__ C,
                                                 int K, int Nn,
                                                 const float* __restrict__ bias,
                                                 const float* __restrict__ C2) {
    __shared__ __align__(16) uint32_t As[64][36];
    __shared__ __align__(16) uint32_t Bs[32][72];
    int m0 = blockIdx.y * 64, n0 = blockIdx.x * 64;
    int tid = threadIdx.x, lane = tid & 31, warp = tid >> 5;
    int wm = (warp & 3) * 16, wn = (warp >> 2) * 32;
    int g = lane >> 2, t = lane & 3;

    int am = tid >> 3, akq = tid & 7;
    int bk = tid >> 4, bn4 = tid & 15;

    float4 pa[2], pb[2];
    #pragma unroll
    for (int it = 0; it < 2; it++) {
        pa[it] = *(const float4*)(A + (size_t)(m0 + am + it * 32) * K + akq * 4);
        pb[it] = *(const float4*)(B + (size_t)(bk + it * 16) * Nn + n0 + bn4 * 4);
    }
    float acc[4][4];
    #pragma unroll
    for (int i = 0; i < 4; i++)
        #pragma unroll
        for (int j = 0; j < 4; j++) acc[i][j] = 0.f;

    for (int kt = 0; kt < K; kt += 32) {
        __syncthreads();
        #pragma unroll
        for (int it = 0; it < 2; it++) {
            uint32_t* ap = &As[am + it * 32][akq * 4];
            ap[0] = f2tf(pa[it].x); ap[1] = f2tf(pa[it].y);
            ap[2] = f2tf(pa[it].z); ap[3] = f2tf(pa[it].w);
            uint32_t* bp = &Bs[bk + it * 16][bn4 * 4];
            bp[0] = f2tf(pb[it].x); bp[1] = f2tf(pb[it].y);
            bp[2] = f2tf(pb[it].z); bp[3] = f2tf(pb[it].w);
        }
        __syncthreads();
        if (kt + 32 < K) {
            #pragma unroll
            for (int it = 0; it < 2; it++) {
                pa[it] = *(const float4*)(A + (size_t)(m0 + am + it * 32) * K + kt + 32 + akq * 4);
                pb[it] = *(const float4*)(B + (size_t)(kt + 32 + bk + it * 16) * Nn + n0 + bn4 * 4);
            }
        }
        #pragma unroll
        for (int k8 = 0; k8 < 32; k8 += 8) {
            uint32_t a[4] = {As[wm + g][k8 + t],     As[wm + g + 8][k8 + t],
                             As[wm + g][k8 + t + 4], As[wm + g + 8][k8 + t + 4]};
            #pragma unroll
            for (int nt = 0; nt < 4; nt++) {
                uint32_t b[2] = {Bs[k8 + t][wn + nt * 8 + g], Bs[k8 + t + 4][wn + nt * 8 + g]};
                mma_tf32(acc[nt], a, b);
            }
        }
    }
    #pragma unroll
    for (int nt = 0; nt < 4; nt++) {
        int col = n0 + wn + nt * 8 + t * 2;
        #pragma unroll
        for (int half = 0; half < 2; half++) {
            int row = m0 + wm + g + half * 8;
            float v0 = acc[nt][half * 2 + 0], v1 = acc[nt][half * 2 + 1];
            if (EPI == 4) { v0 *= C2[(size_t)row * Nn + col]; v1 *= C2[(size_t)row * Nn + col + 1]; }
            C[(size_t)row * Nn + col]     = v0;
            C[(size_t)row * Nn + col + 1] = v1;
        }
    }
}

// ---------------- fused AdaLN ----------------
__global__ __launch_bounds__(256) void adaln_tf32(const float* __restrict__ SN,
                                                  const float* __restrict__ Wgam,
                                                  const float* __restrict__ gb,
                                                  const float* __restrict__ Wsh,
                                                  const float* __restrict__ AN,
                                                  float* __restrict__ A2) {
    __shared__ __align__(16) uint32_t As[64][36];
    __shared__ __align__(16) uint32_t B1s[32][72];
    __shared__ __align__(16) uint32_t B2s[32][72];
    const int K = S_, Nn = A_;
    int m0 = blockIdx.y * 64, n0 = blockIdx.x * 64;
    int tid = threadIdx.x, lane = tid & 31, warp = tid >> 5;
    int wm = (warp & 3) * 16, wn = (warp >> 2) * 32;
    int g = lane >> 2, t = lane & 3;

    int am = tid >> 3, akq = tid & 7;
    int bk = tid >> 4, bn4 = tid & 15;

    float4 pa[2], pb1[2], pb2[2];
    #pragma unroll
    for (int it = 0; it < 2; it++) {
        pa[it]  = *(const float4*)(SN   + (size_t)(m0 + am + it * 32) * K + akq * 4);
        pb1[it] = *(const float4*)(Wgam + (size_t)(bk + it * 16) * Nn + n0 + bn4 * 4);
        pb2[it] = *(const float4*)(Wsh  + (size_t)(bk + it * 16) * Nn + n0 + bn4 * 4);
    }
    float acc1[4][4], acc2[4][4];
    #pragma unroll
    for (int i = 0; i < 4; i++)
        #pragma unroll
        for (int j = 0; j < 4; j++) { acc1[i][j] = 0.f; acc2[i][j] = 0.f; }

    for (int kt = 0; kt < K; kt += 32) {
        __syncthreads();
        #pragma unroll
        for (int it = 0; it < 2; it++) {
            uint32_t* ap = &As[am + it * 32][akq * 4];
            ap[0] = f2tf(pa[it].x); ap[1] = f2tf(pa[it].y);
            ap[2] = f2tf(pa[it].z); ap[3] = f2tf(pa[it].w);
            uint32_t* b1 = &B1s[bk + it * 16][bn4 * 4];
            b1[0] = f2tf(pb1[it].x); b1[1] = f2tf(pb1[it].y);
            b1[2] = f2tf(pb1[it].z); b1[3] = f2tf(pb1[it].w);
            uint32_t* b2 = &B2s[bk + it * 16][bn4 * 4];
            b2[0] = f2tf(pb2[it].x); b2[1] = f2tf(pb2[it].y);
            b2[2] = f2tf(pb2[it].z); b2[3] = f2tf(pb2[it].w);
        }
        __syncthreads();
        if (kt + 32 < K) {
            #pragma unroll
            for (int it = 0; it < 2; it++) {
                pa[it]  = *(const float4*)(SN   + (size_t)(m0 + am + it * 32) * K + kt + 32 + akq * 4);
                pb1[it] = *(const float4*)(Wgam + (size_t)(kt + 32 + bk + it * 16) * Nn + n0 + bn4 * 4);
                pb2[it] = *(const float4*)(Wsh  + (size_t)(kt + 32 + bk + it * 16) * Nn + n0 + bn4 * 4);
            }
        }
        #pragma unroll
        for (int k8 = 0; k8 < 32; k8 += 8) {
            uint32_t a[4] = {As[wm + g][k8 + t],     As[wm + g + 8][k8 + t],
                             As[wm + g][k8 + t + 4], As[wm + g + 8][k8 + t + 4]};
            #pragma unroll
            for (int nt = 0; nt < 4; nt++) {
                uint32_t b1[2] = {B1s[k8 + t][wn + nt * 8 + g], B1s[k8 + t + 4][wn + nt * 8 + g]};
                mma_tf32(acc1[nt], a, b1);
                uint32_t b2[2] = {B2s[k8 + t][wn + nt * 8 + g], B2s[k8 + t + 4][wn + nt * 8 + g]};
                mma_tf32(acc2[nt], a, b2);
            }
        }
    }
    #pragma unroll
    for (int nt = 0; nt < 4; nt++) {
        int col = n0 + wn + nt * 8 + t * 2;
        #pragma unroll
        for (int half = 0; half < 2; half++) {
            int row = m0 + wm + g + half * 8;
            #pragma unroll
            for (int e = 0; e < 2; e++) {
                float gv = sigm(acc1[nt][half * 2 + e] + gb[col + e]);
                float a2 = gv * AN[(size_t)row * Nn + col + e] + acc2[nt][half * 2 + e];
                A2[(size_t)row * Nn + col + e] = a2;
            }
        }
    }
}

// ============================================================================
//  FUSED MID KERNEL — 592 blocks @ 4/SM. GEMM roles then work-stealing pool.
//  Pool uses split-K warps: warp = (row-block, K-half), A-fragments loaded once.
// ============================================================================

__device__ __noinline__ void qkvg2_body(uint32_t* shm, int bx, int by, int zp,
                                        const float* __restrict__ A2,
                                        const float* __restrict__ bq,
                                        const float* __restrict__ B0,
                                        const float* __restrict__ B1,
                                        float* __restrict__ C0,
                                        float* __restrict__ C1) {
    uint32_t* As  = shm;                // [64][36]
    uint32_t* Bs0 = shm + 64 * 36;      // [32][72]
    uint32_t* Bs1 = Bs0 + 32 * 72;      // [32][72]
    const int K = A_, Nn = A_;

    int m0 = by * 64, n0 = bx * 64;
    int tid = threadIdx.x, lane = tid & 31, warp = tid >> 5;
    int wm = (warp & 3) * 16, wn = (warp >> 2) * 32;
    int g = lane >> 2, t = lane & 3;
    int am = tid >> 3, akq = tid & 7;
    int bk = tid >> 4, bn4 = tid & 15;

    float acc0[4][4], acc1[4][4];
    #pragma unroll
    for (int i = 0; i < 4; i++)
        #pragma unroll
        for (int j = 0; j < 4; j++) { acc0[i][j] = 0.f; acc1[i][j] = 0.f; }

    for (int kt = 0; kt < K; kt += 32) {
        __syncthreads();
        #pragma unroll
        for (int it = 0; it < 2; it++) {
            float4 pa  = *(const float4*)(A2 + (size_t)(m0 + am + it * 32) * K + kt + akq * 4);
            float4 pb0 = *(const float4*)(B0 + (size_t)(kt + bk + it * 16) * Nn + n0 + bn4 * 4);
            float4 pb1 = *(const float4*)(B1 + (size_t)(kt + bk + it * 16) * Nn + n0 + bn4 * 4);
            uint32_t* ap = &As[(am + it * 32) * 36 + akq * 4];
            ap[0] = f2tf(pa.x); ap[1] = f2tf(pa.y);
            ap[2] = f2tf(pa.z); ap[3] = f2tf(pa.w);
            uint32_t* b0 = &Bs0[(bk + it * 16) * 72 + bn4 * 4];
            b0[0] = f2tf(pb0.x); b0[1] = f2tf(pb0.y);
            b0[2] = f2tf(pb0.z); b0[3] = f2tf(pb0.w);
            uint32_t* b1 = &Bs1[(bk + it * 16) * 72 + bn4 * 4];
            b1[0] = f2tf(pb1.x); b1[1] = f2tf(pb1.y);
            b1[2] = f2tf(pb1.z); b1[3] = f2tf(pb1.w);
        }
        __syncthreads();
        #pragma unroll
        for (int k8 = 0; k8 < 32; k8 += 8) {
            uint32_t a[4] = {As[(wm + g) * 36 + k8 + t],     As[(wm + g + 8) * 36 + k8 + t],
                             As[(wm + g) * 36 + k8 + t + 4], As[(wm + g + 8) * 36 + k8 + t + 4]};
            #pragma unroll
            for (int nt = 0; nt < 4; nt++) {
                uint32_t b0[2] = {Bs0[(k8 + t) * 72 + wn + nt * 8 + g],
                                  Bs0[(k8 + t + 4) * 72 + wn + nt * 8 + g]};
                mma_tf32(acc0[nt], a, b0);
                uint32_t b1[2] = {Bs1[(k8 + t) * 72 + wn + nt * 8 + g],
                                  Bs1[(k8 + t + 4) * 72 + wn + nt * 8 + g]};
                mma_tf32(acc1[nt], a, b1);
            }
        }
    }
    #pragma unroll
    for (int nt = 0; nt < 4; nt++) {
        int col = n0 + wn + nt * 8 + t * 2;
        #pragma unroll
        for (int half = 0; half < 2; half++) {
            int row = m0 + wm + g + half * 8;
            #pragma unroll
            for (int e = 0; e < 2; e++) {
                float v0 = acc0[nt][half * 2 + e];
                float v1 = acc1[nt][half * 2 + e];
                if (zp == 0) v0 += bq[col + e];     // q gets bias
                if (zp == 1) v1 = sigm(v1);         // g gets sigmoid
                C0[(size_t)row * Nn + col + e] = v0;
                C1[(size_t)row * Nn + col + e] = v1;
            }
        }
    }
}

__device__ __noinline__ void gate_body(uint32_t* shm, int bx, int by,
                                       const float* __restrict__ A,
                                       const float* __restrict__ B,
                                       const float* __restrict__ bias,
                                       float* __restrict__ C) {
    uint32_t* As = shm;
    uint32_t* Bs = shm + 64 * 36;
    const int K = S_, Nn = A_;
    int m0 = by * 64, n0 = bx * 64;
    int tid = threadIdx.x, lane = tid & 31, warp = tid >> 5;
    int wm = (warp & 3) * 16, wn = (warp >> 2) * 32;
    int g = lane >> 2, t = lane & 3;
    int am = tid >> 3, akq = tid & 7;
    int bk = tid >> 4, bn4 = tid & 15;

    float acc[4][4];
    #pragma unroll
    for (int i = 0; i < 4; i++)
        #pragma unroll
        for (int j = 0; j < 4; j++) acc[i][j] = 0.f;

    for (int kt = 0; kt < K; kt += 32) {
        __syncthreads();
        #pragma unroll
        for (int it = 0; it < 2; it++) {
            float4 pa = *(const float4*)(A + (size_t)(m0 + am + it * 32) * K + kt + akq * 4);
            float4 pb = *(const float4*)(B + (size_t)(kt + bk + it * 16) * Nn + n0 + bn4 * 4);
            uint32_t* ap = &As[(am + it * 32) * 36 + akq * 4];
            ap[0] = f2tf(pa.x); ap[1] = f2tf(pa.y);
            ap[2] = f2tf(pa.z); ap[3] = f2tf(pa.w);
            uint32_t* bp = &Bs[(bk + it * 16) * 72 + bn4 * 4];
            bp[0] = f2tf(pb.x); bp[1] = f2tf(pb.y);
            bp[2] = f2tf(pb.z); bp[3] = f2tf(pb.w);
        }
        __syncthreads();
        #pragma unroll
        for (int k8 = 0; k8 < 32; k8 += 8) {
            uint32_t a[4] = {As[(wm + g) * 36 + k8 + t],     As[(wm + g + 8) * 36 + k8 + t],
                             As[(wm + g) * 36 + k8 + t + 4], As[(wm + g + 8) * 36 + k8 + t + 4]};
            #pragma unroll
            for (int nt = 0; nt < 4; nt++) {
                uint32_t b[2] = {Bs[(k8 + t) * 72 + wn + nt * 8 + g],
                                 Bs[(k8 + t + 4) * 72 + wn + nt * 8 + g]};
                mma_tf32(acc[nt], a, b);
            }
        }
    }
    #pragma unroll
    for (int nt = 0; nt < 4; nt++) {
        int col = n0 + wn + nt * 8 + t * 2;
        #pragma unroll
        for (int half = 0; half < 2; half++) {
            int row = m0 + wm + g + half * 8;
            float v0 = sigm(acc[nt][half * 2 + 0] + bias[col]);
            float v1 = sigm(acc[nt][half * 2 + 1] + bias[col + 1]);
            C[(size_t)row * Nn + col]     = v0;
            C[(size_t)row * Nn + col + 1] = v1;
        }
    }
}

// --- pairbias pool: split-K warps (A-frags loaded once), claim-ahead stealing ---
__device__ __noinline__ void pairbias_pool(uint32_t* shm,
                                           const float* __restrict__ pair,
                                           const float* __restrict__ beta,
                                           const float* __restrict__ w,
                                           const float* __restrict__ b,
                                           const float* __restrict__ Wb,
                                           float* __restrict__ bias) {
    uint32_t* As = shm;             // [64*140]
    uint32_t* Bs = shm + 64 * 140;  // [128*24]
    float*    cmb = (float*)shm;    // [4][32][8] staging; aliases As (free after mma)
    __shared__ unsigned int s_tile;

    int tid = threadIdx.x, lane = tid & 31, warp = tid >> 5;
    int r  = tid >> 2;
    int pq = tid & 3;
    int g = lane >> 2, t = lane & 3;
    int rb = warp & 3;              // row block 0..3
    int wm = rb * 16;
    int kh = warp >> 2;             // K-half 0/1: k8 in [8*kh, 8*kh+8)
    const unsigned int NT = NN / 64;       // 9216 tiles

    __syncthreads();                        // smem handoff from GEMM role
    for (int i = tid; i < P_ * H_; i += 256) {
        int kk = i >> 4, nn = i & 15;
        Bs[kk * 24 + nn] = f2tf(__ldg(Wb + i));
    }

    if (tid == 0) s_tile = atomicAdd(&d_pbctr, 1u);
    __syncthreads();
    unsigned int tile = s_tile;

    while (tile < NT) {
        // claim + L2-prefetch NEXT tile (32KB = 256 threads x 128B)
        if (tid == 0) s_tile = atomicAdd(&d_pbctr, 1u);
        __syncthreads();                    // broadcast; prev combine done (As free)
        unsigned int nxt = s_tile;
        if (nxt < NT) {
            const char* pp = (const char*)(pair + (size_t)nxt * 64 * P_) + tid * 128;
            asm volatile("prefetch.global.L2 [%0];" :: "l"(pp));
        }

        const float* row = pair + ((size_t)tile * 64 + r) * P_;
        float4 u[4][2];
        #pragma unroll
        for (int j = 0; j < 4; j++) {
            u[j][0] = *(const float4*)(row + 8 * pq + 32 * j);
            u[j][1] = *(const float4*)(row + 8 * pq + 32 * j + 4);
        }

        float s = 0.f, s2 = 0.f;
        #pragma unroll
        for (int j = 0; j < 4; j++)
            #pragma unroll
            for (int h2 = 0; h2 < 2; h2++) {
                const float4 f = u[j][h2];
                s  += f.x + f.y + f.z + f.w;
                s2 += f.x * f.x + f.y * f.y + f.z * f.z + f.w * f.w;
            }
        s  += __shfl_xor_sync(0xffffffffu, s, 1);  s  += __shfl_xor_sync(0xffffffffu, s, 2);
        s2 += __shfl_xor_sync(0xffffffffu, s2, 1); s2 += __shfl_xor_sync(0xffffffffu, s2, 2);
        float mean = s * (1.f / P_);
        float var  = s2 * (1.f / P_) - mean * mean;
        float rs   = rsqrtf(var + 1e-5f);

        #pragma unroll
        for (int j = 0; j < 4; j++) {
            int c0 = 8 * pq + 32 * j;
            #pragma unroll
            for (int h2 = 0; h2 < 2; h2++) {
                const float4 wv = *(const float4*)(w + c0 + 4 * h2);
                const float4 bv = *(const float4*)(b + c0 + 4 * h2);
                const float4 f  = u[j][h2];
                uint4 pkt;
                pkt.x = f2tf((f.x - mean) * rs * wv.x + bv.x);
                pkt.y = f2tf((f.y - mean) * rs * wv.y + bv.y);
                pkt.z = f2tf((f.z - mean) * rs * wv.z + bv.z);
                pkt.w = f2tf((f.w - mean) * rs * wv.w + bv.w);
                *(uint4*)&As[r * 140 + c0 + 4 * h2] = pkt;
            }
        }
        __syncthreads();                    // As ready for mma

        // mma: warp(rb,kh) -> rows wm..wm+15, its K-half, ALL 16 heads
        float acc0[4] = {0.f, 0.f, 0.f, 0.f};
        float acc1[4] = {0.f, 0.f, 0.f, 0.f};
        #pragma unroll
        for (int kk = 0; kk < 8; kk++) {
            int k = (kh * 8 + kk) * 8;
            uint32_t a[4] = {As[(wm + g) * 140 + k + t],     As[(wm + g + 8) * 140 + k + t],
                             As[(wm + g) * 140 + k + t + 4], As[(wm + g + 8) * 140 + k + t + 4]};
            uint32_t b0[2] = {Bs[(k + t) * 24 + g],     Bs[(k + t + 4) * 24 + g]};
            mma_tf32(acc0, a, b0);
            uint32_t b1[2] = {Bs[(k + t) * 24 + 8 + g], Bs[(k + t + 4) * 24 + 8 + g]};
            mma_tf32(acc1, a, b1);
        }
        __syncthreads();                    // all mma done; As area reusable as cmb

        float* cslot = cmb + (rb * 32 + lane) * 8;
        if (kh == 1) {
            *(float4*)(cslot)     = make_float4(acc0[0], acc0[1], acc0[2], acc0[3]);
            *(float4*)(cslot + 4) = make_float4(acc1[0], acc1[1], acc1[2], acc1[3]);
        }
        __syncthreads();
        if (kh == 0) {
            float4 c0 = *(float4*)(cslot);
            float4 c1 = *(float4*)(cslot + 4);
            acc0[0] += c0.x; acc0[1] += c0.y; acc0[2] += c0.z; acc0[3] += c0.w;
            acc1[0] += c1.x; acc1[1] += c1.y; acc1[2] += c1.z; acc1[3] += c1.w;
            int p0 = tile * 64;
            int pr0 = p0 + wm + g, pr1 = pr0 + 8;
            float be0 = __ldg(beta + pr0), be1 = __ldg(beta + pr1);
            int h0 = 2 * t;
            bias[(size_t)(h0)     * NN + pr0] = acc0[0] + be0;
            bias[(size_t)(h0 + 1) * NN + pr0] = acc0[1] + be0;
            bias[(size_t)(h0)     * NN + pr1] = acc0[2] + be1;
            bias[(size_t)(h0 + 1) * NN + pr1] = acc0[3] + be1;
            bias[(size_t)(h0 + 8) * NN + pr0] = acc1[0] + be0;
            bias[(size_t)(h0 + 9) * NN + pr0] = acc1[1] + be0;
            bias[(size_t)(h0 + 8) * NN + pr1] = acc1[2] + be1;
            bias[(size_t)(h0 + 9) * NN + pr1] = acc1[3] + be1;
        }
        tile = nxt;
    }
}

#define FUSED_SMEM ((64*140 + 128*24)*4)
#define FUSED_GRID 592

__global__ __launch_bounds__(256, 4) void fused_mid(
    const float* __restrict__ A2,
    const float* __restrict__ Wq, const float* __restrict__ bq,
    const float* __restrict__ Wk, const float* __restrict__ Wv,
    const float* __restrict__ Wg,
    float* __restrict__ oq, float* __restrict__ ok,
    float* __restrict__ ov, float* __restrict__ og,
    const float* __restrict__ sIn, const float* __restrict__ Wout,
    const float* __restrict__ bout, float* __restrict__ gate,
    const float* __restrict__ pair, const float* __restrict__ beta,
    const float* __restrict__ lnpw, const float* __restrict__ lnpb,
    const float* __restrict__ Wb, float* __restrict__ bias) {
    extern __shared__ __align__(16) uint32_t shm[];
    int bx = blockIdx.x;
    if (bx < 144) {
        qkvg2_body(shm, bx % 12, bx / 12, 0, A2, bq, Wq, Wk, oq, ok);
    } else if (bx < 288) {
        int i = bx - 144;
        qkvg2_body(shm, i % 12, i / 12, 1, A2, bq, Wv, Wg, ov, og);
    } else if (bx < 432) {
        int i = bx - 288;
        gate_body(shm, i % 12, i / 12, sIn, Wout, bout, gate);
    }
    pairbias_pool(shm, pair, beta, lnpw, lnpb, Wb, bias);
}

// ---------------- flash attention, split-KV x2, 64 q-rows / 4 warps ----------------
#define AQ(r,c) smQ[(r)*52+(c)]
#define AK(r,c) smK[(r)*52+(c)]
#define AV(r,c) smV[(r)*56+(c)]
#define AP(r,c) smP[(r)*68+(c)]
#define ATTN_SMEM (64*(52+52+56+68)*4)

__global__ __launch_bounds__(128) void attn_tf32(const float* __restrict__ q,
                                                 const float* __restrict__ k,
                                                 const float* __restrict__ v,
                                                 const float* __restrict__ bias,
                                                 float* __restrict__ opart,
                                                 float2* __restrict__ mlv) {
    extern __shared__ uint32_t sm[];
    uint32_t* smQ = sm;
    uint32_t* smK = smQ + 64 * 52;
    uint32_t* smV = smK + 64 * 52;
    uint32_t* smP = smV + 64 * 56;

    int h  = blockIdx.y;
    int q0 = blockIdx.x * 64;
    int sidx = blockIdx.z;
    int s0 = sidx * (N_ / 2);
    int tid = threadIdx.x, lane = tid & 31, warp = tid >> 5;
    int g = lane >> 2, t = lane & 3;
    int wm = warp * 16;

    #pragma unroll
    for (int it = 0; it < 6; it++) {
        int idx = tid + it * 128;
        int r = idx / 12, c4 = idx % 12;
        float4 v4 = *(const float4*)(q + (size_t)(q0 + r) * A_ + h * D_ + c4 * 4);
        AQ(r, c4 * 4 + 0) = f2tf(v4.x); AQ(r, c4 * 4 + 1) = f2tf(v4.y);
        AQ(r, c4 * 4 + 2) = f2tf(v4.z); AQ(r, c4 * 4 + 3) = f2tf(v4.w);
    }

    float m0 = -1e30f, m1 = -1e30f, l0 = 0.f, l1 = 0.f;
    float oacc[6][4];
    #pragma unroll
    for (int dt = 0; dt < 6; dt++)
        #pragma unroll
        for (int e = 0; e < 4; e++) oacc[dt][e] = 0.f;

    const float scale = 0.144337567f;

    for (int j0 = s0; j0 < s0 + N_ / 2; j0 += 64) {
        __syncthreads();

        const float* bp0 = bias + (size_t)h * NN + (size_t)(q0 + wm + g) * N_ + j0;
        const float* bp1 = bp0 + 8 * N_;
        float2 bpre0[8], bpre1[8];
        #pragma unroll
        for (int nt = 0; nt < 8; nt++) {
            bpre0[nt] = *(const float2*)(bp0 + nt * 8 + 2 * t);
            bpre1[nt] = *(const float2*)(bp1 + nt * 8 + 2 * t);
        }

        #pragma unroll
        for (int it = 0; it < 6; it++) {
            int idx = tid + it * 128;
            int r = idx / 12, c4 = idx % 12;
            float4 kv = *(const float4*)(k + (size_t)(j0 + r) * A_ + h * D_ + c4 * 4);
            AK(r, c4 * 4 + 0) = f2tf(kv.x); AK(r, c4 * 4 + 1) = f2tf(kv.y);
            AK(r, c4 * 4 + 2) = f2tf(kv.z); AK(r, c4 * 4 + 3) = f2tf(kv.w);
            float4 vv = *(const float4*)(v + (size_t)(j0 + r) * A_ + h * D_ + c4 * 4);
            AV(r, c4 * 4 + 0) = f2tf(vv.x); AV(r, c4 * 4 + 1) = f2tf(vv.y);
            AV(r, c4 * 4 + 2) = f2tf(vv.z); AV(r, c4 * 4 + 3) = f2tf(vv.w);
        }
        __syncthreads();

        float sacc[8][4];
        #pragma unroll
        for (int nt = 0; nt < 8; nt++)
            #pragma unroll
            for (int e = 0; e < 4; e++) sacc[nt][e] = 0.f;

        #pragma unroll
        for (int k8 = 0; k8 < 48; k8 += 8) {
            uint32_t a[4] = {AQ(wm + g, k8 + t),     AQ(wm + g + 8, k8 + t),
                             AQ(wm + g, k8 + t + 4), AQ(wm + g + 8, k8 + t + 4)};
            #pragma unroll
            for (int nt = 0; nt < 8; nt++) {
                uint32_t b[2] = {AK(nt * 8 + g, k8 + t), AK(nt * 8 + g, k8 + t + 4)};
                mma_tf32(sacc[nt], a, b);
            }
        }

        #pragma unroll
        for (int nt = 0; nt < 8; nt++) {
            sacc[nt][0] = sacc[nt][0] * scale + bpre0[nt].x;
            sacc[nt][1] = sacc[nt][1] * scale + bpre0[nt].y;
            sacc[nt][2] = sacc[nt][2] * scale + bpre1[nt].x;
            sacc[nt][3] = sacc[nt][3] * scale + bpre1[nt].y;
        }

        float mx0 = -1e30f, mx1 = -1e30f;
        #pragma unroll
        for (int nt = 0; nt < 8; nt++) {
            mx0 = fmaxf(mx0, fmaxf(sacc[nt][0], sacc[nt][1]));
            mx1 = fmaxf(mx1, fmaxf(sacc[nt][2], sacc[nt][3]));
        }
        mx0 = fmaxf(mx0, __shfl_xor_sync(0xffffffffu, mx0, 1));
        mx0 = fmaxf(mx0, __shfl_xor_sync(0xffffffffu, mx0, 2));
        mx1 = fmaxf(mx1, __shfl_xor_sync(0xffffffffu, mx1, 1));
        mx1 = fmaxf(mx1, __shfl_xor_sync(0xffffffffu, mx1, 2));
        float mn0 = fmaxf(m0, mx0), mn1 = fmaxf(m1, mx1);
        float cr0 = __expf(m0 - mn0), cr1 = __expf(m1 - mn1);
        m0 = mn0; m1 = mn1;

        float s0r = 0.f, s1r = 0.f;
        #pragma unroll
        for (int nt = 0; nt < 8; nt++) {
            float p00 = __expf(sacc[nt][0] - mn0);
            float p01 = __expf(sacc[nt][1] - mn0);
            float p10 = __expf(sacc[nt][2] - mn1);
            float p11 = __expf(sacc[nt][3] - mn1);
            s0r += p00 + p01; s1r += p10 + p11;
            int c = nt * 8 + 2 * t;
            AP(wm + g, c)         = f2tf(p00);
            AP(wm + g, c + 1)     = f2tf(p01);
            AP(wm + g + 8, c)     = f2tf(p10);
            AP(wm + g + 8, c + 1) = f2tf(p11);
        }
        s0r += __shfl_xor_sync(0xffffffffu, s0r, 1);
        s0r += __shfl_xor_sync(0xffffffffu, s0r, 2);
        s1r += __shfl_xor_sync(0xffffffffu, s1r, 1);
        s1r += __shfl_xor_sync(0xffffffffu, s1r, 2);
        l0 = l0 * cr0 + s0r;
        l1 = l1 * cr1 + s1r;

        #pragma unroll
        for (int dt = 0; dt < 6; dt++) {
            oacc[dt][0] *= cr0; oacc[dt][1] *= cr0;
            oacc[dt][2] *= cr1; oacc[dt][3] *= cr1;
        }
        __syncwarp();

        #pragma unroll
        for (int k8 = 0; k8 < 64; k8 += 8) {
            uint32_t a[4] = {AP(wm + g, k8 + t),     AP(wm + g + 8, k8 + t),
                             AP(wm + g, k8 + t + 4), AP(wm + g + 8, k8 + t + 4)};
            #pragma unroll
            for (int dt = 0; dt < 6; dt++) {
                uint32_t b[2] = {AV(k8 + t, dt * 8 + g), AV(k8 + t + 4, dt * 8 + g)};
                mma_tf32(oacc[dt], a, b);
            }
        }
    }

    float* op = opart + (size_t)sidx * N_ * A_;
    int r0 = q0 + wm + g, r1 = r0 + 8;
    #pragma unroll
    for (int dt = 0; dt < 6; dt++) {
        int d = dt * 8 + 2 * t;
        size_t i00 = (size_t)r0 * A_ + h * D_ + d;
        size_t i10 = (size_t)r1 * A_ + h * D_ + d;
        op[i00]     = oacc[dt][0];
        op[i00 + 1] = oacc[dt][1];
        op[i10]     = oacc[dt][2];
        op[i10 + 1] = oacc[dt][3];
    }
    if (t == 0) {
        mlv[(size_t)sidx * H_ * N_ + h * N_ + r0] = make_float2(m0, l0);
        mlv[(size_t)sidx * H_ * N_ + h * N_ + r1] = make_float2(m1, l1);
    }
}

// ---------------- merge split-KV partials + gate ----------------
__global__ __launch_bounds__(256) void attn_merge(const float* __restrict__ op,
                                                  const float2* __restrict__ ml,
                                                  const float* __restrict__ gt,
                                                  float* __restrict__ o) {
    int idx = blockIdx.x * 256 + threadIdx.x;
    int n  = idx / 192;
    int c4 = idx - n * 192;
    int h  = c4 / 12;
    float2 ml1 = ml[h * N_ + n];
    float2 ml2 = ml[H_ * N_ + h * N_ + n];
    float m  = fmaxf(ml1.x, ml2.x);
    float w1 = __expf(ml1.x - m), w2 = __expf(ml2.x - m);
    float inv = 1.f / (w1 * ml1.y + w2 * ml2.y);
    size_t off = (size_t)n * A_ + c4 * 4;
    const float4 a1 = *(const float4*)(op + off);
    const float4 a2 = *(const float4*)(op + (size_t)N_ * A_ + off);
    const float4 g4 = *(const float4*)(gt + off);
    float4 r;
    r.x = (w1 * a1.x + w2 * a2.x) * inv * g4.x;
    r.y = (w1 * a1.y + w2 * a2.y) * inv * g4.y;
    r.z = (w1 * a1.z + w2 * a2.z) * inv * g4.z;
    r.w = (w1 * a1.w + w2 * a2.w) * inv * g4.w;
    *(float4*)(o + off) = r;
}

// ---------------- launch ----------------
extern "C" void kernel_launch(void* const* d_in, const int* in_sizes, int n_in,
                              void* d_out, int out_size) {
    const float* a       = (const float*)d_in[0];
    const float* s       = (const float*)d_in[1];
    const float* pair    = (const float*)d_in[2];
    const float* beta    = (const float*)d_in[3];
    const float* ln_s_w  = (const float*)d_in[4];
    const float* gamma_w = (const float*)d_in[5];
    const float* gamma_b = (const float*)d_in[6];
    const float* shift_w = (const float*)d_in[7];
    const float* Wq      = (const float*)d_in[8];
    const float* bq      = (const float*)d_in[9];
    const float* Wk      = (const float*)d_in[10];
    const float* Wv      = (const float*)d_in[11];
    const float* ln_p_w  = (const float*)d_in[12];
    const float* ln_p_b  = (const float*)d_in[13];
    const float* Wb      = (const float*)d_in[14];
    const float* Wg      = (const float*)d_in[15];
    const float* Wp      = (const float*)d_in[16];
    const float* Wout    = (const float*)d_in[17];
    const float* bout    = (const float*)d_in[18];
    float* out = (float*)d_out;

    float *p_sn, *p_an, *p_a2, *p_q, *p_k, *p_v, *p_gt, *p_bias, *p_o, *p_gate, *p_opart;
    float2 *p_ml;
    cudaGetSymbolAddress((void**)&p_sn,    d_sn);
    cudaGetSymbolAddress((void**)&p_an,    d_an);
    cudaGetSymbolAddress((void**)&p_a2,    d_a2);
    cudaGetSymbolAddress((void**)&p_q,     d_q);
    cudaGetSymbolAddress((void**)&p_k,     d_k);
    cudaGetSymbolAddress((void**)&p_v,     d_v);
    cudaGetSymbolAddress((void**)&p_gt,    d_gt);
    cudaGetSymbolAddress((void**)&p_bias,  d_bias);
    cudaGetSymbolAddress((void**)&p_o,     d_o);
    cudaGetSymbolAddress((void**)&p_gate,  d_gate);
    cudaGetSymbolAddress((void**)&p_opart, d_opart);
    cudaGetSymbolAddress((void**)&p_ml,    d_ml);

    cudaFuncSetAttribute(attn_tf32,  cudaFuncAttributeMaxDynamicSharedMemorySize, ATTN_SMEM);
    cudaFuncSetAttribute(fused_mid,  cudaFuncAttributeMaxDynamicSharedMemorySize, FUSED_SMEM);

    dim3 g2(A_ / 64, N_ / 64);

    ln_kernel<S_, 1><<<N_, 256>>>(s, ln_s_w, p_sn);          // launch 1 (+ctr reset)
    ln_kernel<A_, 0><<<N_, 256>>>(a, nullptr, p_an);         // launch 2
    adaln_tf32<<<g2, 256>>>(p_sn, gamma_w, gamma_b, shift_w, p_an, p_a2);  // launch 3
    fused_mid<<<FUSED_GRID, 256, FUSED_SMEM>>>(              // launch 4 (profiled)
        p_a2, Wq, bq, Wk, Wv, Wg, p_q, p_k, p_v, p_gt,
        s, Wout, bout, p_gate,
        pair, beta, ln_p_w, ln_p_b, Wb, p_bias);
    dim3 ga(N_ / 64, H_, 2);
    attn_tf32<<<ga, 128, ATTN_SMEM>>>(p_q, p_k, p_v, p_bias, p_opart, p_ml);
    attn_merge<<<576, 256>>>(p_opart, p_ml, p_gt, p_o);
    gemm_tf32<4><<<g2, 256>>>(p_o, Wp, out, A_, A_, nullptr, p_gate);
}

// round 15
// speedup vs baseline: 1.1077x; 1.1077x over previous
#include <cuda_runtime.h>
#include <cuda_fp16.h>
#include <math.h>
#include <stdint.h>

#define N_  768
#define A_  768
#define S_  384
#define P_  128
#define H_  16
#define D_  48
#define NN  (N_*N_)

// ---------------- scratch (no allocations allowed) ----------------
__device__ float d_sn [N_*S_];
__device__ float d_an [N_*A_];
__device__ float d_a2 [N_*A_];
__device__ float d_q  [N_*A_];
__device__ float d_k  [N_*A_];
__device__ float d_v  [N_*A_];
__device__ float d_gt [N_*A_];
__device__ float d_bias[H_*NN];         // [H][N][N]
__device__ float d_o  [N_*A_];
__device__ float d_gate[N_*A_];
__device__ float d_opart[2*N_*A_];      // split-KV unnormalized partials
__device__ float2 d_ml[2*H_*N_];        // (m, l) per split/head/row
__device__ unsigned int d_pbctr;        // pairbias work-stealing counter

// ---------------- helpers ----------------
__device__ __forceinline__ uint32_t f2tf(float f) {
    uint32_t u;
    asm("cvt.rna.tf32.f32 %0, %1;" : "=r"(u) : "f"(f));
    return u;
}
__device__ __forceinline__ void mma_tf32(float* c, const uint32_t* a, const uint32_t* b) {
    asm volatile("mma.sync.aligned.m16n8k8.row.col.f32.tf32.tf32.f32 "
                 "{%0,%1,%2,%3}, {%4,%5,%6,%7}, {%8,%9}, {%0,%1,%2,%3};"
                 : "+f"(c[0]), "+f"(c[1]), "+f"(c[2]), "+f"(c[3])
                 : "r"(a[0]), "r"(a[1]), "r"(a[2]), "r"(a[3]), "r"(b[0]), "r"(b[1]));
}
__device__ __forceinline__ void mma_f16(float* c, const uint32_t* a, const uint32_t* b) {
    asm volatile("mma.sync.aligned.m16n8k16.row.col.f32.f16.f16.f32 "
                 "{%0,%1,%2,%3}, {%4,%5,%6,%7}, {%8,%9}, {%0,%1,%2,%3};"
                 : "+f"(c[0]), "+f"(c[1]), "+f"(c[2]), "+f"(c[3])
                 : "r"(a[0]), "r"(a[1]), "r"(a[2]), "r"(a[3]), "r"(b[0]), "r"(b[1]));
}
__device__ __forceinline__ uint32_t packh2(float x, float y) {
    __half2 h = __floats2half2_rn(x, y);
    return *(uint32_t*)&h;
}
__device__ __forceinline__ float sigm(float x) { return 1.f / (1.f + __expf(-x)); }

// ---------------- merged row LayerNorm (s and a in one launch) ----------------
__global__ __launch_bounds__(256) void ln2_kernel(const float* __restrict__ sx,
                                                  const float* __restrict__ lnw,
                                                  float* __restrict__ sny,
                                                  const float* __restrict__ ax,
                                                  float* __restrict__ any) {
    if (blockIdx.x == 0 && blockIdx.y == 0 && threadIdx.x == 0)
        d_pbctr = 0;                     // reset stealing counter for fused_mid
    const float* x; const float* w; float* y; int COLS;
    if (blockIdx.y == 0) { x = sx; w = lnw;     y = sny; COLS = S_; }
    else                 { x = ax; w = nullptr; y = any; COLS = A_; }
    int row = blockIdx.x;
    const float* xr = x + (size_t)row * COLS;
    float s = 0.f, s2 = 0.f;
    for (int c = threadIdx.x; c < COLS; c += blockDim.x) {
        float v = xr[c]; s += v; s2 += v * v;
    }
    __shared__ float red[64];
    #pragma unroll
    for (int o = 16; o; o >>= 1) {
        s  += __shfl_xor_sync(0xffffffffu, s,  o);
        s2 += __shfl_xor_sync(0xffffffffu, s2, o);
    }
    int wid = threadIdx.x >> 5, lid = threadIdx.x & 31;
    if (lid == 0) { red[wid] = s; red[wid + 32] = s2; }
    __syncthreads();
    if (wid == 0) {
        s  = (lid < 8) ? red[lid]      : 0.f;
        s2 = (lid < 8) ? red[lid + 32] : 0.f;
        #pragma unroll
        for (int o = 4; o; o >>= 1) {
            s  += __shfl_xor_sync(0xffffffffu, s,  o);
            s2 += __shfl_xor_sync(0xffffffffu, s2, o);
        }
        if (lid == 0) { red[0] = s; red[1] = s2; }
    }
    __syncthreads();
    float mean = red[0] / COLS;
    float var  = red[1] / COLS - mean * mean;
    float rs   = rsqrtf(var + 1e-5f);
    float* yr = y + (size_t)row * COLS;
    for (int c = threadIdx.x; c < COLS; c += blockDim.x) {
        float v = (xr[c] - mean) * rs;
        if (w) v *= w[c];
        yr[c] = v;
    }
}

// ---------------- generic tf32 GEMM (standalone, for out-proj) ----------------
template<int EPI>
__global__ __launch_bounds__(256) void gemm_tf32(const float* __restrict__ A,
                                                 const float* __restrict__ B,
                                                 float* __restrict__ C,
                                                 int K, int Nn,
                                                 const float* __restrict__ bias,
                                                 const float* __restrict__ C2) {
    __shared__ __align__(16) uint32_t As[64][36];
    __shared__ __align__(16) uint32_t Bs[32][72];
    int m0 = blockIdx.y * 64, n0 = blockIdx.x * 64;
    int tid = threadIdx.x, lane = tid & 31, warp = tid >> 5;
    int wm = (warp & 3) * 16, wn = (warp >> 2) * 32;
    int g = lane >> 2, t = lane & 3;

    int am = tid >> 3, akq = tid & 7;
    int bk = tid >> 4, bn4 = tid & 15;

    float4 pa[2], pb[2];
    #pragma unroll
    for (int it = 0; it < 2; it++) {
        pa[it] = *(const float4*)(A + (size_t)(m0 + am + it * 32) * K + akq * 4);
        pb[it] = *(const float4*)(B + (size_t)(bk + it * 16) * Nn + n0 + bn4 * 4);
    }
    float acc[4][4];
    #pragma unroll
    for (int i = 0; i < 4; i++)
        #pragma unroll
        for (int j = 0; j < 4; j++) acc[i][j] = 0.f;

    for (int kt = 0; kt < K; kt += 32) {
        __syncthreads();
        #pragma unroll
        for (int it = 0; it < 2; it++) {
            uint32_t* ap = &As[am + it * 32][akq * 4];
            ap[0] = f2tf(pa[it].x); ap[1] = f2tf(pa[it].y);
            ap[2] = f2tf(pa[it].z); ap[3] = f2tf(pa[it].w);
            uint32_t* bp = &Bs[bk + it * 16][bn4 * 4];
            bp[0] = f2tf(pb[it].x); bp[1] = f2tf(pb[it].y);
            bp[2] = f2tf(pb[it].z); bp[3] = f2tf(pb[it].w);
        }
        __syncthreads();
        if (kt + 32 < K) {
            #pragma unroll
            for (int it = 0; it < 2; it++) {
                pa[it] = *(const float4*)(A + (size_t)(m0 + am + it * 32) * K + kt + 32 + akq * 4);
                pb[it] = *(const float4*)(B + (size_t)(kt + 32 + bk + it * 16) * Nn + n0 + bn4 * 4);
            }
        }
        #pragma unroll
        for (int k8 = 0; k8 < 32; k8 += 8) {
            uint32_t a[4] = {As[wm + g][k8 + t],     As[wm + g + 8][k8 + t],
                             As[wm + g][k8 + t + 4], As[wm + g + 8][k8 + t + 4]};
            #pragma unroll
            for (int nt = 0; nt < 4; nt++) {
                uint32_t b[2] = {Bs[k8 + t][wn + nt * 8 + g], Bs[k8 + t + 4][wn + nt * 8 + g]};
                mma_tf32(acc[nt], a, b);
            }
        }
    }
    #pragma unroll
    for (int nt = 0; nt < 4; nt++) {
        int col = n0 + wn + nt * 8 + t * 2;
        #pragma unroll
        for (int half = 0; half < 2; half++) {
            int row = m0 + wm + g + half * 8;
            float v0 = acc[nt][half * 2 + 0], v1 = acc[nt][half * 2 + 1];
            if (EPI == 4) { v0 *= C2[(size_t)row * Nn + col]; v1 *= C2[(size_t)row * Nn + col + 1]; }
            C[(size_t)row * Nn + col]     = v0;
            C[(size_t)row * Nn + col + 1] = v1;
        }
    }
}

// ---------------- fused AdaLN ----------------
__global__ __launch_bounds__(256) void adaln_tf32(const float* __restrict__ SN,
                                                  const float* __restrict__ Wgam,
                                                  const float* __restrict__ gb,
                                                  const float* __restrict__ Wsh,
                                                  const float* __restrict__ AN,
                                                  float* __restrict__ A2) {
    __shared__ __align__(16) uint32_t As[64][36];
    __shared__ __align__(16) uint32_t B1s[32][72];
    __shared__ __align__(16) uint32_t B2s[32][72];
    const int K = S_, Nn = A_;
    int m0 = blockIdx.y * 64, n0 = blockIdx.x * 64;
    int tid = threadIdx.x, lane = tid & 31, warp = tid >> 5;
    int wm = (warp & 3) * 16, wn = (warp >> 2) * 32;
    int g = lane >> 2, t = lane & 3;

    int am = tid >> 3, akq = tid & 7;
    int bk = tid >> 4, bn4 = tid & 15;

    float4 pa[2], pb1[2], pb2[2];
    #pragma unroll
    for (int it = 0; it < 2; it++) {
        pa[it]  = *(const float4*)(SN   + (size_t)(m0 + am + it * 32) * K + akq * 4);
        pb1[it] = *(const float4*)(Wgam + (size_t)(bk + it * 16) * Nn + n0 + bn4 * 4);
        pb2[it] = *(const float4*)(Wsh  + (size_t)(bk + it * 16) * Nn + n0 + bn4 * 4);
    }
    float acc1[4][4], acc2[4][4];
    #pragma unroll
    for (int i = 0; i < 4; i++)
        #pragma unroll
        for (int j = 0; j < 4; j++) { acc1[i][j] = 0.f; acc2[i][j] = 0.f; }

    for (int kt = 0; kt < K; kt += 32) {
        __syncthreads();
        #pragma unroll
        for (int it = 0; it < 2; it++) {
            uint32_t* ap = &As[am + it * 32][akq * 4];
            ap[0] = f2tf(pa[it].x); ap[1] = f2tf(pa[it].y);
            ap[2] = f2tf(pa[it].z); ap[3] = f2tf(pa[it].w);
            uint32_t* b1 = &B1s[bk + it * 16][bn4 * 4];
            b1[0] = f2tf(pb1[it].x); b1[1] = f2tf(pb1[it].y);
            b1[2] = f2tf(pb1[it].z); b1[3] = f2tf(pb1[it].w);
            uint32_t* b2 = &B2s[bk + it * 16][bn4 * 4];
            b2[0] = f2tf(pb2[it].x); b2[1] = f2tf(pb2[it].y);
            b2[2] = f2tf(pb2[it].z); b2[3] = f2tf(pb2[it].w);
        }
        __syncthreads();
        if (kt + 32 < K) {
            #pragma unroll
            for (int it = 0; it < 2; it++) {
                pa[it]  = *(const float4*)(SN   + (size_t)(m0 + am + it * 32) * K + kt + 32 + akq * 4);
                pb1[it] = *(const float4*)(Wgam + (size_t)(kt + 32 + bk + it * 16) * Nn + n0 + bn4 * 4);
                pb2[it] = *(const float4*)(Wsh  + (size_t)(kt + 32 + bk + it * 16) * Nn + n0 + bn4 * 4);
            }
        }
        #pragma unroll
        for (int k8 = 0; k8 < 32; k8 += 8) {
            uint32_t a[4] = {As[wm + g][k8 + t],     As[wm + g + 8][k8 + t],
                             As[wm + g][k8 + t + 4], As[wm + g + 8][k8 + t + 4]};
            #pragma unroll
            for (int nt = 0; nt < 4; nt++) {
                uint32_t b1[2] = {B1s[k8 + t][wn + nt * 8 + g], B1s[k8 + t + 4][wn + nt * 8 + g]};
                mma_tf32(acc1[nt], a, b1);
                uint32_t b2[2] = {B2s[k8 + t][wn + nt * 8 + g], B2s[k8 + t + 4][wn + nt * 8 + g]};
                mma_tf32(acc2[nt], a, b2);
            }
        }
    }
    #pragma unroll
    for (int nt = 0; nt < 4; nt++) {
        int col = n0 + wn + nt * 8 + t * 2;
        #pragma unroll
        for (int half = 0; half < 2; half++) {
            int row = m0 + wm + g + half * 8;
            #pragma unroll
            for (int e = 0; e < 2; e++) {
                float gv = sigm(acc1[nt][half * 2 + e] + gb[col + e]);
                float a2 = gv * AN[(size_t)row * Nn + col + e] + acc2[nt][half * 2 + e];
                A2[(size_t)row * Nn + col + e] = a2;
            }
        }
    }
}

// ============================================================================
//  FUSED MID KERNEL — 592 blocks @ 4/SM. GEMM roles then work-stealing pool.
//  Pool uses fp16 mma (m16n8k16): same mantissa as tf32, half the L1 traffic.
// ============================================================================

__device__ __noinline__ void qkvg2_body(uint32_t* shm, int bx, int by, int zp,
                                        const float* __restrict__ A2,
                                        const float* __restrict__ bq,
                                        const float* __restrict__ B0,
                                        const float* __restrict__ B1,
                                        float* __restrict__ C0,
                                        float* __restrict__ C1) {
    uint32_t* As  = shm;                // [64][36]
    uint32_t* Bs0 = shm + 64 * 36;      // [32][72]
    uint32_t* Bs1 = Bs0 + 32 * 72;      // [32][72]
    const int K = A_, Nn = A_;

    int m0 = by * 64, n0 = bx * 64;
    int tid = threadIdx.x, lane = tid & 31, warp = tid >> 5;
    int wm = (warp & 3) * 16, wn = (warp >> 2) * 32;
    int g = lane >> 2, t = lane & 3;
    int am = tid >> 3, akq = tid & 7;
    int bk = tid >> 4, bn4 = tid & 15;

    float acc0[4][4], acc1[4][4];
    #pragma unroll
    for (int i = 0; i < 4; i++)
        #pragma unroll
        for (int j = 0; j < 4; j++) { acc0[i][j] = 0.f; acc1[i][j] = 0.f; }

    for (int kt = 0; kt < K; kt += 32) {
        __syncthreads();
        #pragma unroll
        for (int it = 0; it < 2; it++) {
            float4 pa  = *(const float4*)(A2 + (size_t)(m0 + am + it * 32) * K + kt + akq * 4);
            float4 pb0 = *(const float4*)(B0 + (size_t)(kt + bk + it * 16) * Nn + n0 + bn4 * 4);
            float4 pb1 = *(const float4*)(B1 + (size_t)(kt + bk + it * 16) * Nn + n0 + bn4 * 4);
            uint32_t* ap = &As[(am + it * 32) * 36 + akq * 4];
            ap[0] = f2tf(pa.x); ap[1] = f2tf(pa.y);
            ap[2] = f2tf(pa.z); ap[3] = f2tf(pa.w);
            uint32_t* b0 = &Bs0[(bk + it * 16) * 72 + bn4 * 4];
            b0[0] = f2tf(pb0.x); b0[1] = f2tf(pb0.y);
            b0[2] = f2tf(pb0.z); b0[3] = f2tf(pb0.w);
            uint32_t* b1 = &Bs1[(bk + it * 16) * 72 + bn4 * 4];
            b1[0] = f2tf(pb1.x); b1[1] = f2tf(pb1.y);
            b1[2] = f2tf(pb1.z); b1[3] = f2tf(pb1.w);
        }
        __syncthreads();
        #pragma unroll
        for (int k8 = 0; k8 < 32; k8 += 8) {
            uint32_t a[4] = {As[(wm + g) * 36 + k8 + t],     As[(wm + g + 8) * 36 + k8 + t],
                             As[(wm + g) * 36 + k8 + t + 4], As[(wm + g + 8) * 36 + k8 + t + 4]};
            #pragma unroll
            for (int nt = 0; nt < 4; nt++) {
                uint32_t b0[2] = {Bs0[(k8 + t) * 72 + wn + nt * 8 + g],
                                  Bs0[(k8 + t + 4) * 72 + wn + nt * 8 + g]};
                mma_tf32(acc0[nt], a, b0);
                uint32_t b1[2] = {Bs1[(k8 + t) * 72 + wn + nt * 8 + g],
                                  Bs1[(k8 + t + 4) * 72 + wn + nt * 8 + g]};
                mma_tf32(acc1[nt], a, b1);
            }
        }
    }
    #pragma unroll
    for (int nt = 0; nt < 4; nt++) {
        int col = n0 + wn + nt * 8 + t * 2;
        #pragma unroll
        for (int half = 0; half < 2; half++) {
            int row = m0 + wm + g + half * 8;
            #pragma unroll
            for (int e = 0; e < 2; e++) {
                float v0 = acc0[nt][half * 2 + e];
                float v1 = acc1[nt][half * 2 + e];
                if (zp == 0) v0 += bq[col + e];     // q gets bias
                if (zp == 1) v1 = sigm(v1);         // g gets sigmoid
                C0[(size_t)row * Nn + col + e] = v0;
                C1[(size_t)row * Nn + col + e] = v1;
            }
        }
    }
}

__device__ __noinline__ void gate_body(uint32_t* shm, int bx, int by,
                                       const float* __restrict__ A,
                                       const float* __restrict__ B,
                                       const float* __restrict__ bias,
                                       float* __restrict__ C) {
    uint32_t* As = shm;
    uint32_t* Bs = shm + 64 * 36;
    const int K = S_, Nn = A_;
    int m0 = by * 64, n0 = bx * 64;
    int tid = threadIdx.x, lane = tid & 31, warp = tid >> 5;
    int wm = (warp & 3) * 16, wn = (warp >> 2) * 32;
    int g = lane >> 2, t = lane & 3;
    int am = tid >> 3, akq = tid & 7;
    int bk = tid >> 4, bn4 = tid & 15;

    float acc[4][4];
    #pragma unroll
    for (int i = 0; i < 4; i++)
        #pragma unroll
        for (int j = 0; j < 4; j++) acc[i][j] = 0.f;

    for (int kt = 0; kt < K; kt += 32) {
        __syncthreads();
        #pragma unroll
        for (int it = 0; it < 2; it++) {
            float4 pa = *(const float4*)(A + (size_t)(m0 + am + it * 32) * K + kt + akq * 4);
            float4 pb = *(const float4*)(B + (size_t)(kt + bk + it * 16) * Nn + n0 + bn4 * 4);
            uint32_t* ap = &As[(am + it * 32) * 36 + akq * 4];
            ap[0] = f2tf(pa.x); ap[1] = f2tf(pa.y);
            ap[2] = f2tf(pa.z); ap[3] = f2tf(pa.w);
            uint32_t* bp = &Bs[(bk + it * 16) * 72 + bn4 * 4];
            bp[0] = f2tf(pb.x); bp[1] = f2tf(pb.y);
            bp[2] = f2tf(pb.z); bp[3] = f2tf(pb.w);
        }
        __syncthreads();
        #pragma unroll
        for (int k8 = 0; k8 < 32; k8 += 8) {
            uint32_t a[4] = {As[(wm + g) * 36 + k8 + t],     As[(wm + g + 8) * 36 + k8 + t],
                             As[(wm + g) * 36 + k8 + t + 4], As[(wm + g + 8) * 36 + k8 + t + 4]};
            #pragma unroll
            for (int nt = 0; nt < 4; nt++) {
                uint32_t b[2] = {Bs[(k8 + t) * 72 + wn + nt * 8 + g],
                                 Bs[(k8 + t + 4) * 72 + wn + nt * 8 + g]};
                mma_tf32(acc[nt], a, b);
            }
        }
    }
    #pragma unroll
    for (int nt = 0; nt < 4; nt++) {
        int col = n0 + wn + nt * 8 + t * 2;
        #pragma unroll
        for (int half = 0; half < 2; half++) {
            int row = m0 + wm + g + half * 8;
            float v0 = sigm(acc[nt][half * 2 + 0] + bias[col]);
            float v1 = sigm(acc[nt][half * 2 + 1] + bias[col + 1]);
            C[(size_t)row * Nn + col]     = v0;
            C[(size_t)row * Nn + col + 1] = v1;
        }
    }
}

// --- pairbias pool: fp16 mma (K=16), half the L1 traffic of tf32 version ---
// As16: packed half2 words, row stride 68 (bank 4g+t conflict-free for frags)
// Bsw:  packed half2 K-pairs, stride 24 (banks {0,24,16,8}+g distinct)
__device__ __noinline__ void pairbias_pool(uint32_t* shm,
                                           const float* __restrict__ pair,
                                           const float* __restrict__ beta,
                                           const float* __restrict__ w,
                                           const float* __restrict__ b,
                                           const float* __restrict__ Wb,
                                           float* __restrict__ bias) {
    uint32_t* As16 = shm;               // [64 rows][68 words] (half2)
    uint32_t* Bsw  = shm + 64 * 68;     // [64 kwords][24] (half2)
    __shared__ unsigned int s_tile;

    int tid = threadIdx.x, lane = tid & 31, warp = tid >> 5;
    int r  = tid >> 2;
    int pq = tid & 3;
    int g = lane >> 2, t = lane & 3;
    int wm = (warp & 3) * 16;
    int hh = (warp >> 2) * 8;
    const unsigned int NT = NN / 64;       // 9216 tiles

    __syncthreads();                        // smem handoff from GEMM role
    // Wb -> Bsw: word kw packs K-rows {2kw, 2kw+1} at head h
    for (int i = tid; i < 64 * H_; i += 256) {
        int kw = i >> 4, h = i & 15;
        Bsw[kw * 24 + h] = packh2(__ldg(Wb + (2 * kw) * H_ + h),
                                  __ldg(Wb + (2 * kw + 1) * H_ + h));
    }

    for (;;) {
        if (tid == 0) s_tile = atomicAdd(&d_pbctr, 1u);
        __syncthreads();                    // broadcast tile; prev mma done
        unsigned int tile = s_tile;
        if (tile >= NT) break;

        const float* row = pair + ((size_t)tile * 64 + r) * P_;
        float4 u[4][2];
        #pragma unroll
        for (int j = 0; j < 4; j++) {
            u[j][0] = *(const float4*)(row + 8 * pq + 32 * j);
            u[j][1] = *(const float4*)(row + 8 * pq + 32 * j + 4);
        }
        int p0 = tile * 64;
        float be0 = __ldg(beta + p0 + wm + g);
        float be1 = __ldg(beta + p0 + wm + g + 8);

        float s = 0.f, s2 = 0.f;
        #pragma unroll
        for (int j = 0; j < 4; j++)
            #pragma unroll
            for (int h2 = 0; h2 < 2; h2++) {
                const float4 f = u[j][h2];
                s  += f.x + f.y + f.z + f.w;
                s2 += f.x * f.x + f.y * f.y + f.z * f.z + f.w * f.w;
            }
        s  += __shfl_xor_sync(0xffffffffu, s, 1);  s  += __shfl_xor_sync(0xffffffffu, s, 2);
        s2 += __shfl_xor_sync(0xffffffffu, s2, 1); s2 += __shfl_xor_sync(0xffffffffu, s2, 2);
        float mean = s * (1.f / P_);
        float var  = s2 * (1.f / P_) - mean * mean;
        float rs   = rsqrtf(var + 1e-5f);

        // normalize * w + b -> packed half2 smem (4x STS.128 per thread)
        #pragma unroll
        for (int j = 0; j < 4; j++) {
            int c0 = 8 * pq + 32 * j;
            const float4 wv0 = *(const float4*)(w + c0);
            const float4 bv0 = *(const float4*)(b + c0);
            const float4 wv1 = *(const float4*)(w + c0 + 4);
            const float4 bv1 = *(const float4*)(b + c0 + 4);
            const float4 f0 = u[j][0];
            const float4 f1 = u[j][1];
            float v0 = (f0.x - mean) * rs * wv0.x + bv0.x;
            float v1 = (f0.y - mean) * rs * wv0.y + bv0.y;
            float v2 = (f0.z - mean) * rs * wv0.z + bv0.z;
            float v3 = (f0.w - mean) * rs * wv0.w + bv0.w;
            float v4 = (f1.x - mean) * rs * wv1.x + bv1.x;
            float v5 = (f1.y - mean) * rs * wv1.y + bv1.y;
            float v6 = (f1.z - mean) * rs * wv1.z + bv1.z;
            float v7 = (f1.w - mean) * rs * wv1.w + bv1.w;
            uint4 pkt;
            pkt.x = packh2(v0, v1); pkt.y = packh2(v2, v3);
            pkt.z = packh2(v4, v5); pkt.w = packh2(v6, v7);
            *(uint4*)&As16[r * 68 + 4 * pq + 16 * j] = pkt;
        }
        __syncthreads();                    // As16 ready for mma

        // fp16 mma: warp -> 16 rows x 8 heads, 8 chunks of K=16
        float acc[4] = {0.f, 0.f, 0.f, 0.f};
        #pragma unroll
        for (int c = 0; c < 8; c++) {
            int kw = c * 8;
            uint32_t a[4] = {As16[(wm + g) * 68 + kw + t],     As16[(wm + g + 8) * 68 + kw + t],
                             As16[(wm + g) * 68 + kw + t + 4], As16[(wm + g + 8) * 68 + kw + t + 4]};
            uint32_t bb[2] = {Bsw[(kw + t) * 24 + hh + g], Bsw[(kw + t + 4) * 24 + hh + g]};
            mma_f16(acc, a, bb);
        }

        int pr0 = p0 + wm + g, pr1 = pr0 + 8;
        int h0 = hh + 2 * t;
        bias[(size_t)(h0)     * NN + pr0] = acc[0] + be0;
        bias[(size_t)(h0 + 1) * NN + pr0] = acc[1] + be0;
        bias[(size_t)(h0)     * NN + pr1] = acc[2] + be1;
        bias[(size_t)(h0 + 1) * NN + pr1] = acc[3] + be1;
    }
}

#define FUSED_SMEM ((64*140 + 128*24)*4)   // role max (pool needs less)
#define FUSED_GRID 592

__global__ __launch_bounds__(256, 4) void fused_mid(
    const float* __restrict__ A2,
    const float* __restrict__ Wq, const float* __restrict__ bq,
    const float* __restrict__ Wk, const float* __restrict__ Wv,
    const float* __restrict__ Wg,
    float* __restrict__ oq, float* __restrict__ ok,
    float* __restrict__ ov, float* __restrict__ og,
    const float* __restrict__ sIn, const float* __restrict__ Wout,
    const float* __restrict__ bout, float* __restrict__ gate,
    const float* __restrict__ pair, const float* __restrict__ beta,
    const float* __restrict__ lnpw, const float* __restrict__ lnpb,
    const float* __restrict__ Wb, float* __restrict__ bias) {
    extern __shared__ __align__(16) uint32_t shm[];
    int bx = blockIdx.x;
    if (bx < 144) {
        qkvg2_body(shm, bx % 12, bx / 12, 0, A2, bq, Wq, Wk, oq, ok);
    } else if (bx < 288) {
        int i = bx - 144;
        qkvg2_body(shm, i % 12, i / 12, 1, A2, bq, Wv, Wg, ov, og);
    } else if (bx < 432) {
        int i = bx - 288;
        gate_body(shm, i % 12, i / 12, sIn, Wout, bout, gate);
    }
    pairbias_pool(shm, pair, beta, lnpw, lnpb, Wb, bias);
}

// ---------------- flash attention, split-KV x2, 64 q-rows / 4 warps ----------------
#define AQ(r,c) smQ[(r)*52+(c)]
#define AK(r,c) smK[(r)*52+(c)]
#define AV(r,c) smV[(r)*56+(c)]
#define AP(r,c) smP[(r)*68+(c)]
#define ATTN_SMEM (64*(52+52+56+68)*4)

__global__ __launch_bounds__(128) void attn_tf32(const float* __restrict__ q,
                                                 const float* __restrict__ k,
                                                 const float* __restrict__ v,
                                                 const float* __restrict__ bias,
                                                 float* __restrict__ opart,
                                                 float2* __restrict__ mlv) {
    extern __shared__ uint32_t sm[];
    uint32_t* smQ = sm;
    uint32_t* smK = smQ + 64 * 52;
    uint32_t* smV = smK + 64 * 52;
    uint32_t* smP = smV + 64 * 56;

    int h  = blockIdx.y;
    int q0 = blockIdx.x * 64;
    int sidx = blockIdx.z;
    int s0 = sidx * (N_ / 2);
    int tid = threadIdx.x, lane = tid & 31, warp = tid >> 5;
    int g = lane >> 2, t = lane & 3;
    int wm = warp * 16;

    #pragma unroll
    for (int it = 0; it < 6; it++) {
        int idx = tid + it * 128;
        int r = idx / 12, c4 = idx % 12;
        float4 v4 = *(const float4*)(q + (size_t)(q0 + r) * A_ + h * D_ + c4 * 4);
        AQ(r, c4 * 4 + 0) = f2tf(v4.x); AQ(r, c4 * 4 + 1) = f2tf(v4.y);
        AQ(r, c4 * 4 + 2) = f2tf(v4.z); AQ(r, c4 * 4 + 3) = f2tf(v4.w);
    }

    float m0 = -1e30f, m1 = -1e30f, l0 = 0.f, l1 = 0.f;
    float oacc[6][4];
    #pragma unroll
    for (int dt = 0; dt < 6; dt++)
        #pragma unroll
        for (int e = 0; e < 4; e++) oacc[dt][e] = 0.f;

    const float scale = 0.144337567f;

    for (int j0 = s0; j0 < s0 + N_ / 2; j0 += 64) {
        __syncthreads();

        const float* bp0 = bias + (size_t)h * NN + (size_t)(q0 + wm + g) * N_ + j0;
        const float* bp1 = bp0 + 8 * N_;
        float2 bpre0[8], bpre1[8];
        #pragma unroll
        for (int nt = 0; nt < 8; nt++) {
            bpre0[nt] = *(const float2*)(bp0 + nt * 8 + 2 * t);
            bpre1[nt] = *(const float2*)(bp1 + nt * 8 + 2 * t);
        }

        #pragma unroll
        for (int it = 0; it < 6; it++) {
            int idx = tid + it * 128;
            int r = idx / 12, c4 = idx % 12;
            float4 kv = *(const float4*)(k + (size_t)(j0 + r) * A_ + h * D_ + c4 * 4);
            AK(r, c4 * 4 + 0) = f2tf(kv.x); AK(r, c4 * 4 + 1) = f2tf(kv.y);
            AK(r, c4 * 4 + 2) = f2tf(kv.z); AK(r, c4 * 4 + 3) = f2tf(kv.w);
            float4 vv = *(const float4*)(v + (size_t)(j0 + r) * A_ + h * D_ + c4 * 4);
            AV(r, c4 * 4 + 0) = f2tf(vv.x); AV(r, c4 * 4 + 1) = f2tf(vv.y);
            AV(r, c4 * 4 + 2) = f2tf(vv.z); AV(r, c4 * 4 + 3) = f2tf(vv.w);
        }
        __syncthreads();

        float sacc[8][4];
        #pragma unroll
        for (int nt = 0; nt < 8; nt++)
            #pragma unroll
            for (int e = 0; e < 4; e++) sacc[nt][e] = 0.f;

        #pragma unroll
        for (int k8 = 0; k8 < 48; k8 += 8) {
            uint32_t a[4] = {AQ(wm + g, k8 + t),     AQ(wm + g + 8, k8 + t),
                             AQ(wm + g, k8 + t + 4), AQ(wm + g + 8, k8 + t + 4)};
            #pragma unroll
            for (int nt = 0; nt < 8; nt++) {
                uint32_t b[2] = {AK(nt * 8 + g, k8 + t), AK(nt * 8 + g, k8 + t + 4)};
                mma_tf32(sacc[nt], a, b);
            }
        }

        #pragma unroll
        for (int nt = 0; nt < 8; nt++) {
            sacc[nt][0] = sacc[nt][0] * scale + bpre0[nt].x;
            sacc[nt][1] = sacc[nt][1] * scale + bpre0[nt].y;
            sacc[nt][2] = sacc[nt][2] * scale + bpre1[nt].x;
            sacc[nt][3] = sacc[nt][3] * scale + bpre1[nt].y;
        }

        float mx0 = -1e30f, mx1 = -1e30f;
        #pragma unroll
        for (int nt = 0; nt < 8; nt++) {
            mx0 = fmaxf(mx0, fmaxf(sacc[nt][0], sacc[nt][1]));
            mx1 = fmaxf(mx1, fmaxf(sacc[nt][2], sacc[nt][3]));
        }
        mx0 = fmaxf(mx0, __shfl_xor_sync(0xffffffffu, mx0, 1));
        mx0 = fmaxf(mx0, __shfl_xor_sync(0xffffffffu, mx0, 2));
        mx1 = fmaxf(mx1, __shfl_xor_sync(0xffffffffu, mx1, 1));
        mx1 = fmaxf(mx1, __shfl_xor_sync(0xffffffffu, mx1, 2));
        float mn0 = fmaxf(m0, mx0), mn1 = fmaxf(m1, mx1);
        float cr0 = __expf(m0 - mn0), cr1 = __expf(m1 - mn1);
        m0 = mn0; m1 = mn1;

        float s0r = 0.f, s1r = 0.f;
        #pragma unroll
        for (int nt = 0; nt < 8; nt++) {
            float p00 = __expf(sacc[nt][0] - mn0);
            float p01 = __expf(sacc[nt][1] - mn0);
            float p10 = __expf(sacc[nt][2] - mn1);
            float p11 = __expf(sacc[nt][3] - mn1);
            s0r += p00 + p01; s1r += p10 + p11;
            int c = nt * 8 + 2 * t;
            AP(wm + g, c)         = f2tf(p00);
            AP(wm + g, c + 1)     = f2tf(p01);
            AP(wm + g + 8, c)     = f2tf(p10);
            AP(wm + g + 8, c + 1) = f2tf(p11);
        }
        s0r += __shfl_xor_sync(0xffffffffu, s0r, 1);
        s0r += __shfl_xor_sync(0xffffffffu, s0r, 2);
        s1r += __shfl_xor_sync(0xffffffffu, s1r, 1);
        s1r += __shfl_xor_sync(0xffffffffu, s1r, 2);
        l0 = l0 * cr0 + s0r;
        l1 = l1 * cr1 + s1r;

        #pragma unroll
        for (int dt = 0; dt < 6; dt++) {
            oacc[dt][0] *= cr0; oacc[dt][1] *= cr0;
            oacc[dt][2] *= cr1; oacc[dt][3] *= cr1;
        }
        __syncwarp();

        #pragma unroll
        for (int k8 = 0; k8 < 64; k8 += 8) {
            uint32_t a[4] = {AP(wm + g, k8 + t),     AP(wm + g + 8, k8 + t),
                             AP(wm + g, k8 + t + 4), AP(wm + g + 8, k8 + t + 4)};
            #pragma unroll
            for (int dt = 0; dt < 6; dt++) {
                uint32_t b[2] = {AV(k8 + t, dt * 8 + g), AV(k8 + t + 4, dt * 8 + g)};
                mma_tf32(oacc[dt], a, b);
            }
        }
    }

    float* op = opart + (size_t)sidx * N_ * A_;
    int r0 = q0 + wm + g, r1 = r0 + 8;
    #pragma unroll
    for (int dt = 0; dt < 6; dt++) {
        int d = dt * 8 + 2 * t;
        size_t i00 = (size_t)r0 * A_ + h * D_ + d;
        size_t i10 = (size_t)r1 * A_ + h * D_ + d;
        op[i00]     = oacc[dt][0];
        op[i00 + 1] = oacc[dt][1];
        op[i10]     = oacc[dt][2];
        op[i10 + 1] = oacc[dt][3];
    }
    if (t == 0) {
        mlv[(size_t)sidx * H_ * N_ + h * N_ + r0] = make_float2(m0, l0);
        mlv[(size_t)sidx * H_ * N_ + h * N_ + r1] = make_float2(m1, l1);
    }
}

// ---------------- merge split-KV partials + gate ----------------
__global__ __launch_bounds__(256) void attn_merge(const float* __restrict__ op,
                                                  const float2* __restrict__ ml,
                                                  const float* __restrict__ gt,
                                                  float* __restrict__ o) {
    int idx = blockIdx.x * 256 + threadIdx.x;
    int n  = idx / 192;
    int c4 = idx - n * 192;
    int h  = c4 / 12;
    float2 ml1 = ml[h * N_ + n];
    float2 ml2 = ml[H_ * N_ + h * N_ + n];
    float m  = fmaxf(ml1.x, ml2.x);
    float w1 = __expf(ml1.x - m), w2 = __expf(ml2.x - m);
    float inv = 1.f / (w1 * ml1.y + w2 * ml2.y);
    size_t off = (size_t)n * A_ + c4 * 4;
    const float4 a1 = *(const float4*)(op + off);
    const float4 a2 = *(const float4*)(op + (size_t)N_ * A_ + off);
    const float4 g4 = *(const float4*)(gt + off);
    float4 r;
    r.x = (w1 * a1.x + w2 * a2.x) * inv * g4.x;
    r.y = (w1 * a1.y + w2 * a2.y) * inv * g4.y;
    r.z = (w1 * a1.z + w2 * a2.z) * inv * g4.z;
    r.w = (w1 * a1.w + w2 * a2.w) * inv * g4.w;
    *(float4*)(o + off) = r;
}

// ---------------- launch ----------------
extern "C" void kernel_launch(void* const* d_in, const int* in_sizes, int n_in,
                              void* d_out, int out_size) {
    const float* a       = (const float*)d_in[0];
    const float* s       = (const float*)d_in[1];
    const float* pair    = (const float*)d_in[2];
    const float* beta    = (const float*)d_in[3];
    const float* ln_s_w  = (const float*)d_in[4];
    const float* gamma_w = (const float*)d_in[5];
    const float* gamma_b = (const float*)d_in[6];
    const float* shift_w = (const float*)d_in[7];
    const float* Wq      = (const float*)d_in[8];
    const float* bq      = (const float*)d_in[9];
    const float* Wk      = (const float*)d_in[10];
    const float* Wv      = (const float*)d_in[11];
    const float* ln_p_w  = (const float*)d_in[12];
    const float* ln_p_b  = (const float*)d_in[13];
    const float* Wb      = (const float*)d_in[14];
    const float* Wg      = (const float*)d_in[15];
    const float* Wp      = (const float*)d_in[16];
    const float* Wout    = (const float*)d_in[17];
    const float* bout    = (const float*)d_in[18];
    float* out = (float*)d_out;

    float *p_sn, *p_an, *p_a2, *p_q, *p_k, *p_v, *p_gt, *p_bias, *p_o, *p_gate, *p_opart;
    float2 *p_ml;
    cudaGetSymbolAddress((void**)&p_sn,    d_sn);
    cudaGetSymbolAddress((void**)&p_an,    d_an);
    cudaGetSymbolAddress((void**)&p_a2,    d_a2);
    cudaGetSymbolAddress((void**)&p_q,     d_q);
    cudaGetSymbolAddress((void**)&p_k,     d_k);
    cudaGetSymbolAddress((void**)&p_v,     d_v);
    cudaGetSymbolAddress((void**)&p_gt,    d_gt);
    cudaGetSymbolAddress((void**)&p_bias,  d_bias);
    cudaGetSymbolAddress((void**)&p_o,     d_o);
    cudaGetSymbolAddress((void**)&p_gate,  d_gate);
    cudaGetSymbolAddress((void**)&p_opart, d_opart);
    cudaGetSymbolAddress((void**)&p_ml,    d_ml);

    cudaFuncSetAttribute(attn_tf32,  cudaFuncAttributeMaxDynamicSharedMemorySize, ATTN_SMEM);
    cudaFuncSetAttribute(fused_mid,  cudaFuncAttributeMaxDynamicSharedMemorySize, FUSED_SMEM);

    dim3 g2(A_ / 64, N_ / 64);

    ln2_kernel<<<dim3(N_, 2), 256>>>(s, ln_s_w, p_sn, a, p_an);
    adaln_tf32<<<g2, 256>>>(p_sn, gamma_w, gamma_b, shift_w, p_an, p_a2);
    fused_mid<<<FUSED_GRID, 256, FUSED_SMEM>>>(
        p_a2, Wq, bq, Wk, Wv, Wg, p_q, p_k, p_v, p_gt,
        s, Wout, bout, p_gate,
        pair, beta, ln_p_w, ln_p_b, Wb, p_bias);
    dim3 ga(N_ / 64, H_, 2);
    attn_tf32<<<ga, 128, ATTN_SMEM>>>(p_q, p_k, p_v, p_bias, p_opart, p_ml);
    attn_merge<<<576, 256>>>(p_opart, p_ml, p_gt, p_o);
    gemm_tf32<4><<<g2, 256>>>(p_o, Wp, out, A_, A_, nullptr, p_gate);
}

// round 16
// speedup vs baseline: 1.2067x; 1.0894x over previous
#include <cuda_runtime.h>
#include <cuda_fp16.h>
#include <math.h>
#include <stdint.h>

#define N_  768
#define A_  768
#define S_  384
#define P_  128
#define H_  16
#define D_  48
#define NN  (N_*N_)

// ---------------- scratch (no allocations allowed) ----------------
__device__ float d_sn [N_*S_];
__device__ float d_an [N_*A_];
__device__ float d_a2 [N_*A_];
__device__ float d_q  [N_*A_];
__device__ float d_k  [N_*A_];
__device__ float d_v  [N_*A_];
__device__ float d_gt [N_*A_];
__device__ float d_bias[H_*NN];         // [H][N][N]
__device__ float d_o  [N_*A_];
__device__ float d_gate[N_*A_];
__device__ float d_opart[2*N_*A_];      // split-KV unnormalized partials
__device__ float2 d_ml[2*H_*N_];        // (m, l) per split/head/row
__device__ unsigned int d_pbctr;        // pairbias work-stealing counter

// ---------------- helpers ----------------
__device__ __forceinline__ uint32_t f2tf(float f) {
    uint32_t u;
    asm("cvt.rna.tf32.f32 %0, %1;" : "=r"(u) : "f"(f));
    return u;
}
__device__ __forceinline__ void mma_tf32(float* c, const uint32_t* a, const uint32_t* b) {
    asm volatile("mma.sync.aligned.m16n8k8.row.col.f32.tf32.tf32.f32 "
                 "{%0,%1,%2,%3}, {%4,%5,%6,%7}, {%8,%9}, {%0,%1,%2,%3};"
                 : "+f"(c[0]), "+f"(c[1]), "+f"(c[2]), "+f"(c[3])
                 : "r"(a[0]), "r"(a[1]), "r"(a[2]), "r"(a[3]), "r"(b[0]), "r"(b[1]));
}
__device__ __forceinline__ void mma_f16(float* c, const uint32_t* a, const uint32_t* b) {
    asm volatile("mma.sync.aligned.m16n8k16.row.col.f32.f16.f16.f32 "
                 "{%0,%1,%2,%3}, {%4,%5,%6,%7}, {%8,%9}, {%0,%1,%2,%3};"
                 : "+f"(c[0]), "+f"(c[1]), "+f"(c[2]), "+f"(c[3])
                 : "r"(a[0]), "r"(a[1]), "r"(a[2]), "r"(a[3]), "r"(b[0]), "r"(b[1]));
}
__device__ __forceinline__ uint32_t packh2(float x, float y) {
    __half2 h = __floats2half2_rn(x, y);
    return *(uint32_t*)&h;
}
__device__ __forceinline__ float sigm(float x) { return 1.f / (1.f + __expf(-x)); }

// ---------------- merged row LayerNorm (s and a in one launch) ----------------
__global__ __launch_bounds__(256) void ln2_kernel(const float* __restrict__ sx,
                                                  const float* __restrict__ lnw,
                                                  float* __restrict__ sny,
                                                  const float* __restrict__ ax,
                                                  float* __restrict__ any) {
    if (blockIdx.x == 0 && blockIdx.y == 0 && threadIdx.x == 0)
        d_pbctr = 0;
    const float* x; const float* w; float* y; int COLS;
    if (blockIdx.y == 0) { x = sx; w = lnw;     y = sny; COLS = S_; }
    else                 { x = ax; w = nullptr; y = any; COLS = A_; }
    int row = blockIdx.x;
    const float* xr = x + (size_t)row * COLS;
    float s = 0.f, s2 = 0.f;
    for (int c = threadIdx.x; c < COLS; c += blockDim.x) {
        float v = xr[c]; s += v; s2 += v * v;
    }
    __shared__ float red[64];
    #pragma unroll
    for (int o = 16; o; o >>= 1) {
        s  += __shfl_xor_sync(0xffffffffu, s,  o);
        s2 += __shfl_xor_sync(0xffffffffu, s2, o);
    }
    int wid = threadIdx.x >> 5, lid = threadIdx.x & 31;
    if (lid == 0) { red[wid] = s; red[wid + 32] = s2; }
    __syncthreads();
    if (wid == 0) {
        s  = (lid < 8) ? red[lid]      : 0.f;
        s2 = (lid < 8) ? red[lid + 32] : 0.f;
        #pragma unroll
        for (int o = 4; o; o >>= 1) {
            s  += __shfl_xor_sync(0xffffffffu, s,  o);
            s2 += __shfl_xor_sync(0xffffffffu, s2, o);
        }
        if (lid == 0) { red[0] = s; red[1] = s2; }
    }
    __syncthreads();
    float mean = red[0] / COLS;
    float var  = red[1] / COLS - mean * mean;
    float rs   = rsqrtf(var + 1e-5f);
    float* yr = y + (size_t)row * COLS;
    for (int c = threadIdx.x; c < COLS; c += blockDim.x) {
        float v = (xr[c] - mean) * rs;
        if (w) v *= w[c];
        yr[c] = v;
    }
}

// ============================================================================
// fp16 GEMM building blocks (64x64 tile, BK=32 floats = 16 packed words)
// As16 [64][20], Bsw [16][72]; fragment banks conflict-free (20g+t / 8t+g)
// ============================================================================

// ---------------- standalone fp16 GEMM, EPI 4 = x*C2 (out-proj) ----------------
__global__ __launch_bounds__(256) void gemm_f16(const float* __restrict__ A,
                                                const float* __restrict__ B,
                                                float* __restrict__ C,
                                                int K, int Nn,
                                                const float* __restrict__ C2) {
    __shared__ __align__(16) uint32_t As16[64 * 20];
    __shared__ __align__(16) uint32_t Bsw[16 * 72];
    int m0 = blockIdx.y * 64, n0 = blockIdx.x * 64;
    int tid = threadIdx.x, lane = tid & 31, warp = tid >> 5;
    int wm = (warp & 3) * 16, wn = (warp >> 2) * 32;
    int g = lane >> 2, t = lane & 3;
    int am = tid >> 3, akq = tid & 7;
    int bkw = tid >> 4, bn4 = tid & 15;

    float acc[4][4];
    #pragma unroll
    for (int i = 0; i < 4; i++)
        #pragma unroll
        for (int j = 0; j < 4; j++) acc[i][j] = 0.f;

    for (int kt = 0; kt < K; kt += 32) {
        __syncthreads();
        #pragma unroll
        for (int it = 0; it < 2; it++) {
            float4 pa = *(const float4*)(A + (size_t)(m0 + am + it * 32) * K + kt + akq * 4);
            uint2 wo; wo.x = packh2(pa.x, pa.y); wo.y = packh2(pa.z, pa.w);
            *(uint2*)&As16[(am + it * 32) * 20 + akq * 2] = wo;
        }
        {
            float4 b0 = *(const float4*)(B + (size_t)(kt + 2 * bkw)     * Nn + n0 + bn4 * 4);
            float4 b1 = *(const float4*)(B + (size_t)(kt + 2 * bkw + 1) * Nn + n0 + bn4 * 4);
            uint4 pkt;
            pkt.x = packh2(b0.x, b1.x); pkt.y = packh2(b0.y, b1.y);
            pkt.z = packh2(b0.z, b1.z); pkt.w = packh2(b0.w, b1.w);
            *(uint4*)&Bsw[bkw * 72 + bn4 * 4] = pkt;
        }
        __syncthreads();
        #pragma unroll
        for (int c = 0; c < 2; c++) {
            int kw0 = c * 8;
            uint32_t a[4] = {As16[(wm + g) * 20 + kw0 + t],     As16[(wm + g + 8) * 20 + kw0 + t],
                             As16[(wm + g) * 20 + kw0 + t + 4], As16[(wm + g + 8) * 20 + kw0 + t + 4]};
            #pragma unroll
            for (int nt = 0; nt < 4; nt++) {
                uint32_t b[2] = {Bsw[(kw0 + t) * 72 + wn + nt * 8 + g],
                                 Bsw[(kw0 + t + 4) * 72 + wn + nt * 8 + g]};
                mma_f16(acc[nt], a, b);
            }
        }
    }
    #pragma unroll
    for (int nt = 0; nt < 4; nt++) {
        int col = n0 + wn + nt * 8 + t * 2;
        #pragma unroll
        for (int half = 0; half < 2; half++) {
            int row = m0 + wm + g + half * 8;
            float v0 = acc[nt][half * 2 + 0] * C2[(size_t)row * Nn + col];
            float v1 = acc[nt][half * 2 + 1] * C2[(size_t)row * Nn + col + 1];
            C[(size_t)row * Nn + col]     = v0;
            C[(size_t)row * Nn + col + 1] = v1;
        }
    }
}

// ---------------- fused AdaLN (fp16 dual-B) ----------------
__global__ __launch_bounds__(256) void adaln_f16(const float* __restrict__ SN,
                                                 const float* __restrict__ Wgam,
                                                 const float* __restrict__ gb,
                                                 const float* __restrict__ Wsh,
                                                 const float* __restrict__ AN,
                                                 float* __restrict__ A2) {
    __shared__ __align__(16) uint32_t As16[64 * 20];
    __shared__ __align__(16) uint32_t B1w[16 * 72];
    __shared__ __align__(16) uint32_t B2w[16 * 72];
    const int K = S_, Nn = A_;
    int m0 = blockIdx.y * 64, n0 = blockIdx.x * 64;
    int tid = threadIdx.x, lane = tid & 31, warp = tid >> 5;
    int wm = (warp & 3) * 16, wn = (warp >> 2) * 32;
    int g = lane >> 2, t = lane & 3;
    int am = tid >> 3, akq = tid & 7;
    int bkw = tid >> 4, bn4 = tid & 15;

    float acc1[4][4], acc2[4][4];
    #pragma unroll
    for (int i = 0; i < 4; i++)
        #pragma unroll
        for (int j = 0; j < 4; j++) { acc1[i][j] = 0.f; acc2[i][j] = 0.f; }

    for (int kt = 0; kt < K; kt += 32) {
        __syncthreads();
        #pragma unroll
        for (int it = 0; it < 2; it++) {
            float4 pa = *(const float4*)(SN + (size_t)(m0 + am + it * 32) * K + kt + akq * 4);
            uint2 wo; wo.x = packh2(pa.x, pa.y); wo.y = packh2(pa.z, pa.w);
            *(uint2*)&As16[(am + it * 32) * 20 + akq * 2] = wo;
        }
        {
            float4 g0 = *(const float4*)(Wgam + (size_t)(kt + 2 * bkw)     * Nn + n0 + bn4 * 4);
            float4 g1 = *(const float4*)(Wgam + (size_t)(kt + 2 * bkw + 1) * Nn + n0 + bn4 * 4);
            uint4 p1;
            p1.x = packh2(g0.x, g1.x); p1.y = packh2(g0.y, g1.y);
            p1.z = packh2(g0.z, g1.z); p1.w = packh2(g0.w, g1.w);
            *(uint4*)&B1w[bkw * 72 + bn4 * 4] = p1;
            float4 s0 = *(const float4*)(Wsh + (size_t)(kt + 2 * bkw)     * Nn + n0 + bn4 * 4);
            float4 s1 = *(const float4*)(Wsh + (size_t)(kt + 2 * bkw + 1) * Nn + n0 + bn4 * 4);
            uint4 p2;
            p2.x = packh2(s0.x, s1.x); p2.y = packh2(s0.y, s1.y);
            p2.z = packh2(s0.z, s1.z); p2.w = packh2(s0.w, s1.w);
            *(uint4*)&B2w[bkw * 72 + bn4 * 4] = p2;
        }
        __syncthreads();
        #pragma unroll
        for (int c = 0; c < 2; c++) {
            int kw0 = c * 8;
            uint32_t a[4] = {As16[(wm + g) * 20 + kw0 + t],     As16[(wm + g + 8) * 20 + kw0 + t],
                             As16[(wm + g) * 20 + kw0 + t + 4], As16[(wm + g + 8) * 20 + kw0 + t + 4]};
            #pragma unroll
            for (int nt = 0; nt < 4; nt++) {
                uint32_t b1[2] = {B1w[(kw0 + t) * 72 + wn + nt * 8 + g],
                                  B1w[(kw0 + t + 4) * 72 + wn + nt * 8 + g]};
                mma_f16(acc1[nt], a, b1);
                uint32_t b2[2] = {B2w[(kw0 + t) * 72 + wn + nt * 8 + g],
                                  B2w[(kw0 + t + 4) * 72 + wn + nt * 8 + g]};
                mma_f16(acc2[nt], a, b2);
            }
        }
    }
    #pragma unroll
    for (int nt = 0; nt < 4; nt++) {
        int col = n0 + wn + nt * 8 + t * 2;
        #pragma unroll
        for (int half = 0; half < 2; half++) {
            int row = m0 + wm + g + half * 8;
            #pragma unroll
            for (int e = 0; e < 2; e++) {
                float gv = sigm(acc1[nt][half * 2 + e] + gb[col + e]);
                float a2 = gv * AN[(size_t)row * Nn + col + e] + acc2[nt][half * 2 + e];
                A2[(size_t)row * Nn + col + e] = a2;
            }
        }
    }
}

// ============================================================================
//  FUSED MID KERNEL — 592 blocks @ 4/SM. fp16 GEMM roles + fp16 stealing pool.
// ============================================================================

__device__ __noinline__ void qkvg2_body(uint32_t* shm, int bx, int by, int zp,
                                        const float* __restrict__ A2,
                                        const float* __restrict__ bq,
                                        const float* __restrict__ B0,
                                        const float* __restrict__ B1,
                                        float* __restrict__ C0,
                                        float* __restrict__ C1) {
    uint32_t* As16 = shm;               // [64][20]
    uint32_t* B0w  = shm + 64 * 20;     // [16][72]
    uint32_t* B1w  = B0w + 16 * 72;     // [16][72]
    const int K = A_, Nn = A_;

    int m0 = by * 64, n0 = bx * 64;
    int tid = threadIdx.x, lane = tid & 31, warp = tid >> 5;
    int wm = (warp & 3) * 16, wn = (warp >> 2) * 32;
    int g = lane >> 2, t = lane & 3;
    int am = tid >> 3, akq = tid & 7;
    int bkw = tid >> 4, bn4 = tid & 15;

    float acc0[4][4], acc1[4][4];
    #pragma unroll
    for (int i = 0; i < 4; i++)
        #pragma unroll
        for (int j = 0; j < 4; j++) { acc0[i][j] = 0.f; acc1[i][j] = 0.f; }

    for (int kt = 0; kt < K; kt += 32) {
        __syncthreads();
        #pragma unroll
        for (int it = 0; it < 2; it++) {
            float4 pa = *(const float4*)(A2 + (size_t)(m0 + am + it * 32) * K + kt + akq * 4);
            uint2 wo; wo.x = packh2(pa.x, pa.y); wo.y = packh2(pa.z, pa.w);
            *(uint2*)&As16[(am + it * 32) * 20 + akq * 2] = wo;
        }
        {
            float4 b00 = *(const float4*)(B0 + (size_t)(kt + 2 * bkw)     * Nn + n0 + bn4 * 4);
            float4 b01 = *(const float4*)(B0 + (size_t)(kt + 2 * bkw + 1) * Nn + n0 + bn4 * 4);
            uint4 p0;
            p0.x = packh2(b00.x, b01.x); p0.y = packh2(b00.y, b01.y);
            p0.z = packh2(b00.z, b01.z); p0.w = packh2(b00.w, b01.w);
            *(uint4*)&B0w[bkw * 72 + bn4 * 4] = p0;
            float4 b10 = *(const float4*)(B1 + (size_t)(kt + 2 * bkw)     * Nn + n0 + bn4 * 4);
            float4 b11 = *(const float4*)(B1 + (size_t)(kt + 2 * bkw + 1) * Nn + n0 + bn4 * 4);
            uint4 p1;
            p1.x = packh2(b10.x, b11.x); p1.y = packh2(b10.y, b11.y);
            p1.z = packh2(b10.z, b11.z); p1.w = packh2(b10.w, b11.w);
            *(uint4*)&B1w[bkw * 72 + bn4 * 4] = p1;
        }
        __syncthreads();
        #pragma unroll
        for (int c = 0; c < 2; c++) {
            int kw0 = c * 8;
            uint32_t a[4] = {As16[(wm + g) * 20 + kw0 + t],     As16[(wm + g + 8) * 20 + kw0 + t],
                             As16[(wm + g) * 20 + kw0 + t + 4], As16[(wm + g + 8) * 20 + kw0 + t + 4]};
            #pragma unroll
            for (int nt = 0; nt < 4; nt++) {
                uint32_t b0[2] = {B0w[(kw0 + t) * 72 + wn + nt * 8 + g],
                                  B0w[(kw0 + t + 4) * 72 + wn + nt * 8 + g]};
                mma_f16(acc0[nt], a, b0);
                uint32_t b1[2] = {B1w[(kw0 + t) * 72 + wn + nt * 8 + g],
                                  B1w[(kw0 + t + 4) * 72 + wn + nt * 8 + g]};
                mma_f16(acc1[nt], a, b1);
            }
        }
    }
    #pragma unroll
    for (int nt = 0; nt < 4; nt++) {
        int col = n0 + wn + nt * 8 + t * 2;
        #pragma unroll
        for (int half = 0; half < 2; half++) {
            int row = m0 + wm + g + half * 8;
            #pragma unroll
            for (int e = 0; e < 2; e++) {
                float v0 = acc0[nt][half * 2 + e];
                float v1 = acc1[nt][half * 2 + e];
                if (zp == 0) v0 += bq[col + e];     // q gets bias
                if (zp == 1) v1 = sigm(v1);         // g gets sigmoid
                C0[(size_t)row * Nn + col + e] = v0;
                C1[(size_t)row * Nn + col + e] = v1;
            }
        }
    }
}

__device__ __noinline__ void gate_body(uint32_t* shm, int bx, int by,
                                       const float* __restrict__ A,
                                       const float* __restrict__ B,
                                       const float* __restrict__ bias,
                                       float* __restrict__ C) {
    uint32_t* As16 = shm;
    uint32_t* Bsw  = shm + 64 * 20;
    const int K = S_, Nn = A_;
    int m0 = by * 64, n0 = bx * 64;
    int tid = threadIdx.x, lane = tid & 31, warp = tid >> 5;
    int wm = (warp & 3) * 16, wn = (warp >> 2) * 32;
    int g = lane >> 2, t = lane & 3;
    int am = tid >> 3, akq = tid & 7;
    int bkw = tid >> 4, bn4 = tid & 15;

    float acc[4][4];
    #pragma unroll
    for (int i = 0; i < 4; i++)
        #pragma unroll
        for (int j = 0; j < 4; j++) acc[i][j] = 0.f;

    for (int kt = 0; kt < K; kt += 32) {
        __syncthreads();
        #pragma unroll
        for (int it = 0; it < 2; it++) {
            float4 pa = *(const float4*)(A + (size_t)(m0 + am + it * 32) * K + kt + akq * 4);
            uint2 wo; wo.x = packh2(pa.x, pa.y); wo.y = packh2(pa.z, pa.w);
            *(uint2*)&As16[(am + it * 32) * 20 + akq * 2] = wo;
        }
        {
            float4 b0 = *(const float4*)(B + (size_t)(kt + 2 * bkw)     * Nn + n0 + bn4 * 4);
            float4 b1 = *(const float4*)(B + (size_t)(kt + 2 * bkw + 1) * Nn + n0 + bn4 * 4);
            uint4 pkt;
            pkt.x = packh2(b0.x, b1.x); pkt.y = packh2(b0.y, b1.y);
            pkt.z = packh2(b0.z, b1.z); pkt.w = packh2(b0.w, b1.w);
            *(uint4*)&Bsw[bkw * 72 + bn4 * 4] = pkt;
        }
        __syncthreads();
        #pragma unroll
        for (int c = 0; c < 2; c++) {
            int kw0 = c * 8;
            uint32_t a[4] = {As16[(wm + g) * 20 + kw0 + t],     As16[(wm + g + 8) * 20 + kw0 + t],
                             As16[(wm + g) * 20 + kw0 + t + 4], As16[(wm + g + 8) * 20 + kw0 + t + 4]};
            #pragma unroll
            for (int nt = 0; nt < 4; nt++) {
                uint32_t b[2] = {Bsw[(kw0 + t) * 72 + wn + nt * 8 + g],
                                 Bsw[(kw0 + t + 4) * 72 + wn + nt * 8 + g]};
                mma_f16(acc[nt], a, b);
            }
        }
    }
    #pragma unroll
    for (int nt = 0; nt < 4; nt++) {
        int col = n0 + wn + nt * 8 + t * 2;
        #pragma unroll
        for (int half = 0; half < 2; half++) {
            int row = m0 + wm + g + half * 8;
            float v0 = sigm(acc[nt][half * 2 + 0] + bias[col]);
            float v1 = sigm(acc[nt][half * 2 + 1] + bias[col + 1]);
            C[(size_t)row * Nn + col]     = v0;
            C[(size_t)row * Nn + col + 1] = v1;
        }
    }
}

// --- pairbias pool: fp16 mma (K=16) + work stealing (unchanged from R15) ---
__device__ __noinline__ void pairbias_pool(uint32_t* shm,
                                           const float* __restrict__ pair,
                                           const float* __restrict__ beta,
                                           const float* __restrict__ w,
                                           const float* __restrict__ b,
                                           const float* __restrict__ Wb,
                                           float* __restrict__ bias) {
    uint32_t* As16 = shm;               // [64 rows][68 words]
    uint32_t* Bsw  = shm + 64 * 68;     // [64 kwords][24]
    __shared__ unsigned int s_tile;

    int tid = threadIdx.x, lane = tid & 31, warp = tid >> 5;
    int r  = tid >> 2;
    int pq = tid & 3;
    int g = lane >> 2, t = lane & 3;
    int wm = (warp & 3) * 16;
    int hh = (warp >> 2) * 8;
    const unsigned int NT = NN / 64;

    __syncthreads();                        // smem handoff from GEMM role
    for (int i = tid; i < 64 * H_; i += 256) {
        int kw = i >> 4, h = i & 15;
        Bsw[kw * 24 + h] = packh2(__ldg(Wb + (2 * kw) * H_ + h),
                                  __ldg(Wb + (2 * kw + 1) * H_ + h));
    }

    for (;;) {
        if (tid == 0) s_tile = atomicAdd(&d_pbctr, 1u);
        __syncthreads();
        unsigned int tile = s_tile;
        if (tile >= NT) break;

        const float* row = pair + ((size_t)tile * 64 + r) * P_;
        float4 u[4][2];
        #pragma unroll
        for (int j = 0; j < 4; j++) {
            u[j][0] = *(const float4*)(row + 8 * pq + 32 * j);
            u[j][1] = *(const float4*)(row + 8 * pq + 32 * j + 4);
        }
        int p0 = tile * 64;
        float be0 = __ldg(beta + p0 + wm + g);
        float be1 = __ldg(beta + p0 + wm + g + 8);

        float s = 0.f, s2 = 0.f;
        #pragma unroll
        for (int j = 0; j < 4; j++)
            #pragma unroll
            for (int h2 = 0; h2 < 2; h2++) {
                const float4 f = u[j][h2];
                s  += f.x + f.y + f.z + f.w;
                s2 += f.x * f.x + f.y * f.y + f.z * f.z + f.w * f.w;
            }
        s  += __shfl_xor_sync(0xffffffffu, s, 1);  s  += __shfl_xor_sync(0xffffffffu, s, 2);
        s2 += __shfl_xor_sync(0xffffffffu, s2, 1); s2 += __shfl_xor_sync(0xffffffffu, s2, 2);
        float mean = s * (1.f / P_);
        float var  = s2 * (1.f / P_) - mean * mean;
        float rs   = rsqrtf(var + 1e-5f);

        #pragma unroll
        for (int j = 0; j < 4; j++) {
            int c0 = 8 * pq + 32 * j;
            const float4 wv0 = *(const float4*)(w + c0);
            const float4 bv0 = *(const float4*)(b + c0);
            const float4 wv1 = *(const float4*)(w + c0 + 4);
            const float4 bv1 = *(const float4*)(b + c0 + 4);
            const float4 f0 = u[j][0];
            const float4 f1 = u[j][1];
            float v0 = (f0.x - mean) * rs * wv0.x + bv0.x;
            float v1 = (f0.y - mean) * rs * wv0.y + bv0.y;
            float v2 = (f0.z - mean) * rs * wv0.z + bv0.z;
            float v3 = (f0.w - mean) * rs * wv0.w + bv0.w;
            float v4 = (f1.x - mean) * rs * wv1.x + bv1.x;
            float v5 = (f1.y - mean) * rs * wv1.y + bv1.y;
            float v6 = (f1.z - mean) * rs * wv1.z + bv1.z;
            float v7 = (f1.w - mean) * rs * wv1.w + bv1.w;
            uint4 pkt;
            pkt.x = packh2(v0, v1); pkt.y = packh2(v2, v3);
            pkt.z = packh2(v4, v5); pkt.w = packh2(v6, v7);
            *(uint4*)&As16[r * 68 + 4 * pq + 16 * j] = pkt;
        }
        __syncthreads();

        float acc[4] = {0.f, 0.f, 0.f, 0.f};
        #pragma unroll
        for (int c = 0; c < 8; c++) {
            int kw = c * 8;
            uint32_t a[4] = {As16[(wm + g) * 68 + kw + t],     As16[(wm + g + 8) * 68 + kw + t],
                             As16[(wm + g) * 68 + kw + t + 4], As16[(wm + g + 8) * 68 + kw + t + 4]};
            uint32_t bb[2] = {Bsw[(kw + t) * 24 + hh + g], Bsw[(kw + t + 4) * 24 + hh + g]};
            mma_f16(acc, a, bb);
        }

        int pr0 = p0 + wm + g, pr1 = pr0 + 8;
        int h0 = hh + 2 * t;
        bias[(size_t)(h0)     * NN + pr0] = acc[0] + be0;
        bias[(size_t)(h0 + 1) * NN + pr0] = acc[1] + be0;
        bias[(size_t)(h0)     * NN + pr1] = acc[2] + be1;
        bias[(size_t)(h0 + 1) * NN + pr1] = acc[3] + be1;
    }
}

#define FUSED_SMEM ((64*68 + 64*24)*4)     // pool is now the max role (23.5 KB)
#define FUSED_GRID 592

__global__ __launch_bounds__(256, 4) void fused_mid(
    const float* __restrict__ A2,
    const float* __restrict__ Wq, const float* __restrict__ bq,
    const float* __restrict__ Wk, const float* __restrict__ Wv,
    const float* __restrict__ Wg,
    float* __restrict__ oq, float* __restrict__ ok,
    float* __restrict__ ov, float* __restrict__ og,
    const float* __restrict__ sIn, const float* __restrict__ Wout,
    const float* __restrict__ bout, float* __restrict__ gate,
    const float* __restrict__ pair, const float* __restrict__ beta,
    const float* __restrict__ lnpw, const float* __restrict__ lnpb,
    const float* __restrict__ Wb, float* __restrict__ bias) {
    extern __shared__ __align__(16) uint32_t shm[];
    int bx = blockIdx.x;
    if (bx < 144) {
        qkvg2_body(shm, bx % 12, bx / 12, 0, A2, bq, Wq, Wk, oq, ok);
    } else if (bx < 288) {
        int i = bx - 144;
        qkvg2_body(shm, i % 12, i / 12, 1, A2, bq, Wv, Wg, ov, og);
    } else if (bx < 432) {
        int i = bx - 288;
        gate_body(shm, i % 12, i / 12, sIn, Wout, bout, gate);
    }
    pairbias_pool(shm, pair, beta, lnpw, lnpb, Wb, bias);
}

// ---------------- flash attention, split-KV x2 (tf32, unchanged) ----------------
#define AQ(r,c) smQ[(r)*52+(c)]
#define AK(r,c) smK[(r)*52+(c)]
#define AV(r,c) smV[(r)*56+(c)]
#define AP(r,c) smP[(r)*68+(c)]
#define ATTN_SMEM (64*(52+52+56+68)*4)

__global__ __launch_bounds__(128) void attn_tf32(const float* __restrict__ q,
                                                 const float* __restrict__ k,
                                                 const float* __restrict__ v,
                                                 const float* __restrict__ bias,
                                                 float* __restrict__ opart,
                                                 float2* __restrict__ mlv) {
    extern __shared__ uint32_t sm[];
    uint32_t* smQ = sm;
    uint32_t* smK = smQ + 64 * 52;
    uint32_t* smV = smK + 64 * 52;
    uint32_t* smP = smV + 64 * 56;

    int h  = blockIdx.y;
    int q0 = blockIdx.x * 64;
    int sidx = blockIdx.z;
    int s0 = sidx * (N_ / 2);
    int tid = threadIdx.x, lane = tid & 31, warp = tid >> 5;
    int g = lane >> 2, t = lane & 3;
    int wm = warp * 16;

    #pragma unroll
    for (int it = 0; it < 6; it++) {
        int idx = tid + it * 128;
        int r = idx / 12, c4 = idx % 12;
        float4 v4 = *(const float4*)(q + (size_t)(q0 + r) * A_ + h * D_ + c4 * 4);
        AQ(r, c4 * 4 + 0) = f2tf(v4.x); AQ(r, c4 * 4 + 1) = f2tf(v4.y);
        AQ(r, c4 * 4 + 2) = f2tf(v4.z); AQ(r, c4 * 4 + 3) = f2tf(v4.w);
    }

    float m0 = -1e30f, m1 = -1e30f, l0 = 0.f, l1 = 0.f;
    float oacc[6][4];
    #pragma unroll
    for (int dt = 0; dt < 6; dt++)
        #pragma unroll
        for (int e = 0; e < 4; e++) oacc[dt][e] = 0.f;

    const float scale = 0.144337567f;

    for (int j0 = s0; j0 < s0 + N_ / 2; j0 += 64) {
        __syncthreads();

        const float* bp0 = bias + (size_t)h * NN + (size_t)(q0 + wm + g) * N_ + j0;
        const float* bp1 = bp0 + 8 * N_;
        float2 bpre0[8], bpre1[8];
        #pragma unroll
        for (int nt = 0; nt < 8; nt++) {
            bpre0[nt] = *(const float2*)(bp0 + nt * 8 + 2 * t);
            bpre1[nt] = *(const float2*)(bp1 + nt * 8 + 2 * t);
        }

        #pragma unroll
        for (int it = 0; it < 6; it++) {
            int idx = tid + it * 128;
            int r = idx / 12, c4 = idx % 12;
            float4 kv = *(const float4*)(k + (size_t)(j0 + r) * A_ + h * D_ + c4 * 4);
            AK(r, c4 * 4 + 0) = f2tf(kv.x); AK(r, c4 * 4 + 1) = f2tf(kv.y);
            AK(r, c4 * 4 + 2) = f2tf(kv.z); AK(r, c4 * 4 + 3) = f2tf(kv.w);
            float4 vv = *(const float4*)(v + (size_t)(j0 + r) * A_ + h * D_ + c4 * 4);
            AV(r, c4 * 4 + 0) = f2tf(vv.x); AV(r, c4 * 4 + 1) = f2tf(vv.y);
            AV(r, c4 * 4 + 2) = f2tf(vv.z); AV(r, c4 * 4 + 3) = f2tf(vv.w);
        }
        __syncthreads();

        float sacc[8][4];
        #pragma unroll
        for (int nt = 0; nt < 8; nt++)
            #pragma unroll
            for (int e = 0; e < 4; e++) sacc[nt][e] = 0.f;

        #pragma unroll
        for (int k8 = 0; k8 < 48; k8 += 8) {
            uint32_t a[4] = {AQ(wm + g, k8 + t),     AQ(wm + g + 8, k8 + t),
                             AQ(wm + g, k8 + t + 4), AQ(wm + g + 8, k8 + t + 4)};
            #pragma unroll
            for (int nt = 0; nt < 8; nt++) {
                uint32_t b[2] = {AK(nt * 8 + g, k8 + t), AK(nt * 8 + g, k8 + t + 4)};
                mma_tf32(sacc[nt], a, b);
            }
        }

        #pragma unroll
        for (int nt = 0; nt < 8; nt++) {
            sacc[nt][0] = sacc[nt][0] * scale + bpre0[nt].x;
            sacc[nt][1] = sacc[nt][1] * scale + bpre0[nt].y;
            sacc[nt][2] = sacc[nt][2] * scale + bpre1[nt].x;
            sacc[nt][3] = sacc[nt][3] * scale + bpre1[nt].y;
        }

        float mx0 = -1e30f, mx1 = -1e30f;
        #pragma unroll
        for (int nt = 0; nt < 8; nt++) {
            mx0 = fmaxf(mx0, fmaxf(sacc[nt][0], sacc[nt][1]));
            mx1 = fmaxf(mx1, fmaxf(sacc[nt][2], sacc[nt][3]));
        }
        mx0 = fmaxf(mx0, __shfl_xor_sync(0xffffffffu, mx0, 1));
        mx0 = fmaxf(mx0, __shfl_xor_sync(0xffffffffu, mx0, 2));
        mx1 = fmaxf(mx1, __shfl_xor_sync(0xffffffffu, mx1, 1));
        mx1 = fmaxf(mx1, __shfl_xor_sync(0xffffffffu, mx1, 2));
        float mn0 = fmaxf(m0, mx0), mn1 = fmaxf(m1, mx1);
        float cr0 = __expf(m0 - mn0), cr1 = __expf(m1 - mn1);
        m0 = mn0; m1 = mn1;

        float s0r = 0.f, s1r = 0.f;
        #pragma unroll
        for (int nt = 0; nt < 8; nt++) {
            float p00 = __expf(sacc[nt][0] - mn0);
            float p01 = __expf(sacc[nt][1] - mn0);
            float p10 = __expf(sacc[nt][2] - mn1);
            float p11 = __expf(sacc[nt][3] - mn1);
            s0r += p00 + p01; s1r += p10 + p11;
            int c = nt * 8 + 2 * t;
            AP(wm + g, c)         = f2tf(p00);
            AP(wm + g, c + 1)     = f2tf(p01);
            AP(wm + g + 8, c)     = f2tf(p10);
            AP(wm + g + 8, c + 1) = f2tf(p11);
        }
        s0r += __shfl_xor_sync(0xffffffffu, s0r, 1);
        s0r += __shfl_xor_sync(0xffffffffu, s0r, 2);
        s1r += __shfl_xor_sync(0xffffffffu, s1r, 1);
        s1r += __shfl_xor_sync(0xffffffffu, s1r, 2);
        l0 = l0 * cr0 + s0r;
        l1 = l1 * cr1 + s1r;

        #pragma unroll
        for (int dt = 0; dt < 6; dt++) {
            oacc[dt][0] *= cr0; oacc[dt][1] *= cr0;
            oacc[dt][2] *= cr1; oacc[dt][3] *= cr1;
        }
        __syncwarp();

        #pragma unroll
        for (int k8 = 0; k8 < 64; k8 += 8) {
            uint32_t a[4] = {AP(wm + g, k8 + t),     AP(wm + g + 8, k8 + t),
                             AP(wm + g, k8 + t + 4), AP(wm + g + 8, k8 + t + 4)};
            #pragma unroll
            for (int dt = 0; dt < 6; dt++) {
                uint32_t b[2] = {AV(k8 + t, dt * 8 + g), AV(k8 + t + 4, dt * 8 + g)};
                mma_tf32(oacc[dt], a, b);
            }
        }
    }

    float* op = opart + (size_t)sidx * N_ * A_;
    int r0 = q0 + wm + g, r1 = r0 + 8;
    #pragma unroll
    for (int dt = 0; dt < 6; dt++) {
        int d = dt * 8 + 2 * t;
        size_t i00 = (size_t)r0 * A_ + h * D_ + d;
        size_t i10 = (size_t)r1 * A_ + h * D_ + d;
        op[i00]     = oacc[dt][0];
        op[i00 + 1] = oacc[dt][1];
        op[i10]     = oacc[dt][2];
        op[i10 + 1] = oacc[dt][3];
    }
    if (t == 0) {
        mlv[(size_t)sidx * H_ * N_ + h * N_ + r0] = make_float2(m0, l0);
        mlv[(size_t)sidx * H_ * N_ + h * N_ + r1] = make_float2(m1, l1);
    }
}

// ---------------- merge split-KV partials + gate ----------------
__global__ __launch_bounds__(256) void attn_merge(const float* __restrict__ op,
                                                  const float2* __restrict__ ml,
                                                  const float* __restrict__ gt,
                                                  float* __restrict__ o) {
    int idx = blockIdx.x * 256 + threadIdx.x;
    int n  = idx / 192;
    int c4 = idx - n * 192;
    int h  = c4 / 12;
    float2 ml1 = ml[h * N_ + n];
    float2 ml2 = ml[H_ * N_ + h * N_ + n];
    float m  = fmaxf(ml1.x, ml2.x);
    float w1 = __expf(ml1.x - m), w2 = __expf(ml2.x - m);
    float inv = 1.f / (w1 * ml1.y + w2 * ml2.y);
    size_t off = (size_t)n * A_ + c4 * 4;
    const float4 a1 = *(const float4*)(op + off);
    const float4 a2 = *(const float4*)(op + (size_t)N_ * A_ + off);
    const float4 g4 = *(const float4*)(gt + off);
    float4 r;
    r.x = (w1 * a1.x + w2 * a2.x) * inv * g4.x;
    r.y = (w1 * a1.y + w2 * a2.y) * inv * g4.y;
    r.z = (w1 * a1.z + w2 * a2.z) * inv * g4.z;
    r.w = (w1 * a1.w + w2 * a2.w) * inv * g4.w;
    *(float4*)(o + off) = r;
}

// ---------------- launch ----------------
extern "C" void kernel_launch(void* const* d_in, const int* in_sizes, int n_in,
                              void* d_out, int out_size) {
    const float* a       = (const float*)d_in[0];
    const float* s       = (const float*)d_in[1];
    const float* pair    = (const float*)d_in[2];
    const float* beta    = (const float*)d_in[3];
    const float* ln_s_w  = (const float*)d_in[4];
    const float* gamma_w = (const float*)d_in[5];
    const float* gamma_b = (const float*)d_in[6];
    const float* shift_w = (const float*)d_in[7];
    const float* Wq      = (const float*)d_in[8];
    const float* bq      = (const float*)d_in[9];
    const float* Wk      = (const float*)d_in[10];
    const float* Wv      = (const float*)d_in[11];
    const float* ln_p_w  = (const float*)d_in[12];
    const float* ln_p_b  = (const float*)d_in[13];
    const float* Wb      = (const float*)d_in[14];
    const float* Wg      = (const float*)d_in[15];
    const float* Wp      = (const float*)d_in[16];
    const float* Wout    = (const float*)d_in[17];
    const float* bout    = (const float*)d_in[18];
    float* out = (float*)d_out;

    float *p_sn, *p_an, *p_a2, *p_q, *p_k, *p_v, *p_gt, *p_bias, *p_o, *p_gate, *p_opart;
    float2 *p_ml;
    cudaGetSymbolAddress((void**)&p_sn,    d_sn);
    cudaGetSymbolAddress((void**)&p_an,    d_an);
    cudaGetSymbolAddress((void**)&p_a2,    d_a2);
    cudaGetSymbolAddress((void**)&p_q,     d_q);
    cudaGetSymbolAddress((void**)&p_k,     d_k);
    cudaGetSymbolAddress((void**)&p_v,     d_v);
    cudaGetSymbolAddress((void**)&p_gt,    d_gt);
    cudaGetSymbolAddress((void**)&p_bias,  d_bias);
    cudaGetSymbolAddress((void**)&p_o,     d_o);
    cudaGetSymbolAddress((void**)&p_gate,  d_gate);
    cudaGetSymbolAddress((void**)&p_opart, d_opart);
    cudaGetSymbolAddress((void**)&p_ml,    d_ml);

    cudaFuncSetAttribute(attn_tf32,  cudaFuncAttributeMaxDynamicSharedMemorySize, ATTN_SMEM);
    cudaFuncSetAttribute(fused_mid,  cudaFuncAttributeMaxDynamicSharedMemorySize, FUSED_SMEM);

    dim3 g2(A_ / 64, N_ / 64);

    ln2_kernel<<<dim3(N_, 2), 256>>>(s, ln_s_w, p_sn, a, p_an);
    adaln_f16<<<g2, 256>>>(p_sn, gamma_w, gamma_b, shift_w, p_an, p_a2);
    fused_mid<<<FUSED_GRID, 256, FUSED_SMEM>>>(
        p_a2, Wq, bq, Wk, Wv, Wg, p_q, p_k, p_v, p_gt,
        s, Wout, bout, p_gate,
        pair, beta, ln_p_w, ln_p_b, Wb, p_bias);
    dim3 ga(N_ / 64, H_, 2);
    attn_tf32<<<ga, 128, ATTN_SMEM>>>(p_q, p_k, p_v, p_bias, p_opart, p_ml);
    attn_merge<<<576, 256>>>(p_opart, p_ml, p_gt, p_o);
    gemm_f16<<<g2, 256>>>(p_o, Wp, out, A_, A_, p_gate);
}

// round 17
// speedup vs baseline: 1.2647x; 1.0481x over previous
#include <cuda_runtime.h>
#include <cuda_fp16.h>
#include <math.h>
#include <stdint.h>

#define N_  768
#define A_  768
#define S_  384
#define P_  128
#define H_  16
#define D_  48
#define NN  (N_*N_)

// ---------------- scratch (no allocations allowed) ----------------
__device__ float d_sn [N_*S_];
__device__ float d_an [N_*A_];
__device__ float d_a2 [N_*A_];
__device__ float d_q  [N_*A_];
__device__ float d_k  [N_*A_];
__device__ float d_v  [N_*A_];
__device__ float d_gt [N_*A_];
__device__ float d_bias[H_*NN];         // [H][N][N]
__device__ float d_o  [N_*A_];
__device__ float d_gate[N_*A_];
__device__ float d_opart[2*N_*A_];      // split-KV unnormalized partials
__device__ float2 d_ml[2*H_*N_];        // (m, l) per split/head/row
__device__ unsigned int d_pbctr;        // pairbias work-stealing counter

// ---------------- helpers ----------------
__device__ __forceinline__ void mma_f16(float* c, const uint32_t* a, const uint32_t* b) {
    asm volatile("mma.sync.aligned.m16n8k16.row.col.f32.f16.f16.f32 "
                 "{%0,%1,%2,%3}, {%4,%5,%6,%7}, {%8,%9}, {%0,%1,%2,%3};"
                 : "+f"(c[0]), "+f"(c[1]), "+f"(c[2]), "+f"(c[3])
                 : "r"(a[0]), "r"(a[1]), "r"(a[2]), "r"(a[3]), "r"(b[0]), "r"(b[1]));
}
__device__ __forceinline__ uint32_t packh2(float x, float y) {
    __half2 h = __floats2half2_rn(x, y);
    return *(uint32_t*)&h;
}
__device__ __forceinline__ float sigm(float x) { return 1.f / (1.f + __expf(-x)); }

// ---------------- merged row LayerNorm (s and a in one launch) ----------------
__global__ __launch_bounds__(256) void ln2_kernel(const float* __restrict__ sx,
                                                  const float* __restrict__ lnw,
                                                  float* __restrict__ sny,
                                                  const float* __restrict__ ax,
                                                  float* __restrict__ any) {
    if (blockIdx.x == 0 && blockIdx.y == 0 && threadIdx.x == 0)
        d_pbctr = 0;
    const float* x; const float* w; float* y; int COLS;
    if (blockIdx.y == 0) { x = sx; w = lnw;     y = sny; COLS = S_; }
    else                 { x = ax; w = nullptr; y = any; COLS = A_; }
    int row = blockIdx.x;
    const float* xr = x + (size_t)row * COLS;
    float s = 0.f, s2 = 0.f;
    for (int c = threadIdx.x; c < COLS; c += blockDim.x) {
        float v = xr[c]; s += v; s2 += v * v;
    }
    __shared__ float red[64];
    #pragma unroll
    for (int o = 16; o; o >>= 1) {
        s  += __shfl_xor_sync(0xffffffffu, s,  o);
        s2 += __shfl_xor_sync(0xffffffffu, s2, o);
    }
    int wid = threadIdx.x >> 5, lid = threadIdx.x & 31;
    if (lid == 0) { red[wid] = s; red[wid + 32] = s2; }
    __syncthreads();
    if (wid == 0) {
        s  = (lid < 8) ? red[lid]      : 0.f;
        s2 = (lid < 8) ? red[lid + 32] : 0.f;
        #pragma unroll
        for (int o = 4; o; o >>= 1) {
            s  += __shfl_xor_sync(0xffffffffu, s,  o);
            s2 += __shfl_xor_sync(0xffffffffu, s2, o);
        }
        if (lid == 0) { red[0] = s; red[1] = s2; }
    }
    __syncthreads();
    float mean = red[0] / COLS;
    float var  = red[1] / COLS - mean * mean;
    float rs   = rsqrtf(var + 1e-5f);
    float* yr = y + (size_t)row * COLS;
    for (int c = threadIdx.x; c < COLS; c += blockDim.x) {
        float v = (xr[c] - mean) * rs;
        if (w) v *= w[c];
        yr[c] = v;
    }
}

// ---------------- standalone fp16 GEMM, x*C2 epilogue (out-proj) ----------------
__global__ __launch_bounds__(256) void gemm_f16(const float* __restrict__ A,
                                                const float* __restrict__ B,
                                                float* __restrict__ C,
                                                int K, int Nn,
                                                const float* __restrict__ C2) {
    __shared__ __align__(16) uint32_t As16[64 * 20];
    __shared__ __align__(16) uint32_t Bsw[16 * 72];
    int m0 = blockIdx.y * 64, n0 = blockIdx.x * 64;
    int tid = threadIdx.x, lane = tid & 31, warp = tid >> 5;
    int wm = (warp & 3) * 16, wn = (warp >> 2) * 32;
    int g = lane >> 2, t = lane & 3;
    int am = tid >> 3, akq = tid & 7;
    int bkw = tid >> 4, bn4 = tid & 15;

    float acc[4][4];
    #pragma unroll
    for (int i = 0; i < 4; i++)
        #pragma unroll
        for (int j = 0; j < 4; j++) acc[i][j] = 0.f;

    for (int kt = 0; kt < K; kt += 32) {
        __syncthreads();
        #pragma unroll
        for (int it = 0; it < 2; it++) {
            float4 pa = *(const float4*)(A + (size_t)(m0 + am + it * 32) * K + kt + akq * 4);
            uint2 wo; wo.x = packh2(pa.x, pa.y); wo.y = packh2(pa.z, pa.w);
            *(uint2*)&As16[(am + it * 32) * 20 + akq * 2] = wo;
        }
        {
            float4 b0 = *(const float4*)(B + (size_t)(kt + 2 * bkw)     * Nn + n0 + bn4 * 4);
            float4 b1 = *(const float4*)(B + (size_t)(kt + 2 * bkw + 1) * Nn + n0 + bn4 * 4);
            uint4 pkt;
            pkt.x = packh2(b0.x, b1.x); pkt.y = packh2(b0.y, b1.y);
            pkt.z = packh2(b0.z, b1.z); pkt.w = packh2(b0.w, b1.w);
            *(uint4*)&Bsw[bkw * 72 + bn4 * 4] = pkt;
        }
        __syncthreads();
        #pragma unroll
        for (int c = 0; c < 2; c++) {
            int kw0 = c * 8;
            uint32_t a[4] = {As16[(wm + g) * 20 + kw0 + t],     As16[(wm + g + 8) * 20 + kw0 + t],
                             As16[(wm + g) * 20 + kw0 + t + 4], As16[(wm + g + 8) * 20 + kw0 + t + 4]};
            #pragma unroll
            for (int nt = 0; nt < 4; nt++) {
                uint32_t b[2] = {Bsw[(kw0 + t) * 72 + wn + nt * 8 + g],
                                 Bsw[(kw0 + t + 4) * 72 + wn + nt * 8 + g]};
                mma_f16(acc[nt], a, b);
            }
        }
    }
    #pragma unroll
    for (int nt = 0; nt < 4; nt++) {
        int col = n0 + wn + nt * 8 + t * 2;
        #pragma unroll
        for (int half = 0; half < 2; half++) {
            int row = m0 + wm + g + half * 8;
            float v0 = acc[nt][half * 2 + 0] * C2[(size_t)row * Nn + col];
            float v1 = acc[nt][half * 2 + 1] * C2[(size_t)row * Nn + col + 1];
            C[(size_t)row * Nn + col]     = v0;
            C[(size_t)row * Nn + col + 1] = v1;
        }
    }
}

// ---------------- fused AdaLN (fp16 dual-B) ----------------
__global__ __launch_bounds__(256) void adaln_f16(const float* __restrict__ SN,
                                                 const float* __restrict__ Wgam,
                                                 const float* __restrict__ gb,
                                                 const float* __restrict__ Wsh,
                                                 const float* __restrict__ AN,
                                                 float* __restrict__ A2) {
    __shared__ __align__(16) uint32_t As16[64 * 20];
    __shared__ __align__(16) uint32_t B1w[16 * 72];
    __shared__ __align__(16) uint32_t B2w[16 * 72];
    const int K = S_, Nn = A_;
    int m0 = blockIdx.y * 64, n0 = blockIdx.x * 64;
    int tid = threadIdx.x, lane = tid & 31, warp = tid >> 5;
    int wm = (warp & 3) * 16, wn = (warp >> 2) * 32;
    int g = lane >> 2, t = lane & 3;
    int am = tid >> 3, akq = tid & 7;
    int bkw = tid >> 4, bn4 = tid & 15;

    float acc1[4][4], acc2[4][4];
    #pragma unroll
    for (int i = 0; i < 4; i++)
        #pragma unroll
        for (int j = 0; j < 4; j++) { acc1[i][j] = 0.f; acc2[i][j] = 0.f; }

    for (int kt = 0; kt < K; kt += 32) {
        __syncthreads();
        #pragma unroll
        for (int it = 0; it < 2; it++) {
            float4 pa = *(const float4*)(SN + (size_t)(m0 + am + it * 32) * K + kt + akq * 4);
            uint2 wo; wo.x = packh2(pa.x, pa.y); wo.y = packh2(pa.z, pa.w);
            *(uint2*)&As16[(am + it * 32) * 20 + akq * 2] = wo;
        }
        {
            float4 g0 = *(const float4*)(Wgam + (size_t)(kt + 2 * bkw)     * Nn + n0 + bn4 * 4);
            float4 g1 = *(const float4*)(Wgam + (size_t)(kt + 2 * bkw + 1) * Nn + n0 + bn4 * 4);
            uint4 p1;
            p1.x = packh2(g0.x, g1.x); p1.y = packh2(g0.y, g1.y);
            p1.z = packh2(g0.z, g1.z); p1.w = packh2(g0.w, g1.w);
            *(uint4*)&B1w[bkw * 72 + bn4 * 4] = p1;
            float4 s0 = *(const float4*)(Wsh + (size_t)(kt + 2 * bkw)     * Nn + n0 + bn4 * 4);
            float4 s1 = *(const float4*)(Wsh + (size_t)(kt + 2 * bkw + 1) * Nn + n0 + bn4 * 4);
            uint4 p2;
            p2.x = packh2(s0.x, s1.x); p2.y = packh2(s0.y, s1.y);
            p2.z = packh2(s0.z, s1.z); p2.w = packh2(s0.w, s1.w);
            *(uint4*)&B2w[bkw * 72 + bn4 * 4] = p2;
        }
        __syncthreads();
        #pragma unroll
        for (int c = 0; c < 2; c++) {
            int kw0 = c * 8;
            uint32_t a[4] = {As16[(wm + g) * 20 + kw0 + t],     As16[(wm + g + 8) * 20 + kw0 + t],
                             As16[(wm + g) * 20 + kw0 + t + 4], As16[(wm + g + 8) * 20 + kw0 + t + 4]};
            #pragma unroll
            for (int nt = 0; nt < 4; nt++) {
                uint32_t b1[2] = {B1w[(kw0 + t) * 72 + wn + nt * 8 + g],
                                  B1w[(kw0 + t + 4) * 72 + wn + nt * 8 + g]};
                mma_f16(acc1[nt], a, b1);
                uint32_t b2[2] = {B2w[(kw0 + t) * 72 + wn + nt * 8 + g],
                                  B2w[(kw0 + t + 4) * 72 + wn + nt * 8 + g]};
                mma_f16(acc2[nt], a, b2);
            }
        }
    }
    #pragma unroll
    for (int nt = 0; nt < 4; nt++) {
        int col = n0 + wn + nt * 8 + t * 2;
        #pragma unroll
        for (int half = 0; half < 2; half++) {
            int row = m0 + wm + g + half * 8;
            #pragma unroll
            for (int e = 0; e < 2; e++) {
                float gv = sigm(acc1[nt][half * 2 + e] + gb[col + e]);
                float a2 = gv * AN[(size_t)row * Nn + col + e] + acc2[nt][half * 2 + e];
                A2[(size_t)row * Nn + col + e] = a2;
            }
        }
    }
}

// ============================================================================
//  FUSED MID KERNEL — 592 blocks @ 4/SM. fp16 GEMM roles + fp16 stealing pool.
// ============================================================================

__device__ __noinline__ void qkvg2_body(uint32_t* shm, int bx, int by, int zp,
                                        const float* __restrict__ A2,
                                        const float* __restrict__ bq,
                                        const float* __restrict__ B0,
                                        const float* __restrict__ B1,
                                        float* __restrict__ C0,
                                        float* __restrict__ C1) {
    uint32_t* As16 = shm;               // [64][20]
    uint32_t* B0w  = shm + 64 * 20;     // [16][72]
    uint32_t* B1w  = B0w + 16 * 72;     // [16][72]
    const int K = A_, Nn = A_;

    int m0 = by * 64, n0 = bx * 64;
    int tid = threadIdx.x, lane = tid & 31, warp = tid >> 5;
    int wm = (warp & 3) * 16, wn = (warp >> 2) * 32;
    int g = lane >> 2, t = lane & 3;
    int am = tid >> 3, akq = tid & 7;
    int bkw = tid >> 4, bn4 = tid & 15;

    float acc0[4][4], acc1[4][4];
    #pragma unroll
    for (int i = 0; i < 4; i++)
        #pragma unroll
        for (int j = 0; j < 4; j++) { acc0[i][j] = 0.f; acc1[i][j] = 0.f; }

    for (int kt = 0; kt < K; kt += 32) {
        __syncthreads();
        #pragma unroll
        for (int it = 0; it < 2; it++) {
            float4 pa = *(const float4*)(A2 + (size_t)(m0 + am + it * 32) * K + kt + akq * 4);
            uint2 wo; wo.x = packh2(pa.x, pa.y); wo.y = packh2(pa.z, pa.w);
            *(uint2*)&As16[(am + it * 32) * 20 + akq * 2] = wo;
        }
        {
            float4 b00 = *(const float4*)(B0 + (size_t)(kt + 2 * bkw)     * Nn + n0 + bn4 * 4);
            float4 b01 = *(const float4*)(B0 + (size_t)(kt + 2 * bkw + 1) * Nn + n0 + bn4 * 4);
            uint4 p0;
            p0.x = packh2(b00.x, b01.x); p0.y = packh2(b00.y, b01.y);
            p0.z = packh2(b00.z, b01.z); p0.w = packh2(b00.w, b01.w);
            *(uint4*)&B0w[bkw * 72 + bn4 * 4] = p0;
            float4 b10 = *(const float4*)(B1 + (size_t)(kt + 2 * bkw)     * Nn + n0 + bn4 * 4);
            float4 b11 = *(const float4*)(B1 + (size_t)(kt + 2 * bkw + 1) * Nn + n0 + bn4 * 4);
            uint4 p1;
            p1.x = packh2(b10.x, b11.x); p1.y = packh2(b10.y, b11.y);
            p1.z = packh2(b10.z, b11.z); p1.w = packh2(b10.w, b11.w);
            *(uint4*)&B1w[bkw * 72 + bn4 * 4] = p1;
        }
        __syncthreads();
        #pragma unroll
        for (int c = 0; c < 2; c++) {
            int kw0 = c * 8;
            uint32_t a[4] = {As16[(wm + g) * 20 + kw0 + t],     As16[(wm + g + 8) * 20 + kw0 + t],
                             As16[(wm + g) * 20 + kw0 + t + 4], As16[(wm + g + 8) * 20 + kw0 + t + 4]};
            #pragma unroll
            for (int nt = 0; nt < 4; nt++) {
                uint32_t b0[2] = {B0w[(kw0 + t) * 72 + wn + nt * 8 + g],
                                  B0w[(kw0 + t + 4) * 72 + wn + nt * 8 + g]};
                mma_f16(acc0[nt], a, b0);
                uint32_t b1[2] = {B1w[(kw0 + t) * 72 + wn + nt * 8 + g],
                                  B1w[(kw0 + t + 4) * 72 + wn + nt * 8 + g]};
                mma_f16(acc1[nt], a, b1);
            }
        }
    }
    #pragma unroll
    for (int nt = 0; nt < 4; nt++) {
        int col = n0 + wn + nt * 8 + t * 2;
        #pragma unroll
        for (int half = 0; half < 2; half++) {
            int row = m0 + wm + g + half * 8;
            #pragma unroll
            for (int e = 0; e < 2; e++) {
                float v0 = acc0[nt][half * 2 + e];
                float v1 = acc1[nt][half * 2 + e];
                if (zp == 0) v0 += bq[col + e];
                if (zp == 1) v1 = sigm(v1);
                C0[(size_t)row * Nn + col + e] = v0;
                C1[(size_t)row * Nn + col + e] = v1;
            }
        }
    }
}

__device__ __noinline__ void gate_body(uint32_t* shm, int bx, int by,
                                       const float* __restrict__ A,
                                       const float* __restrict__ B,
                                       const float* __restrict__ bias,
                                       float* __restrict__ C) {
    uint32_t* As16 = shm;
    uint32_t* Bsw  = shm + 64 * 20;
    const int K = S_, Nn = A_;
    int m0 = by * 64, n0 = bx * 64;
    int tid = threadIdx.x, lane = tid & 31, warp = tid >> 5;
    int wm = (warp & 3) * 16, wn = (warp >> 2) * 32;
    int g = lane >> 2, t = lane & 3;
    int am = tid >> 3, akq = tid & 7;
    int bkw = tid >> 4, bn4 = tid & 15;

    float acc[4][4];
    #pragma unroll
    for (int i = 0; i < 4; i++)
        #pragma unroll
        for (int j = 0; j < 4; j++) acc[i][j] = 0.f;

    for (int kt = 0; kt < K; kt += 32) {
        __syncthreads();
        #pragma unroll
        for (int it = 0; it < 2; it++) {
            float4 pa = *(const float4*)(A + (size_t)(m0 + am + it * 32) * K + kt + akq * 4);
            uint2 wo; wo.x = packh2(pa.x, pa.y); wo.y = packh2(pa.z, pa.w);
            *(uint2*)&As16[(am + it * 32) * 20 + akq * 2] = wo;
        }
        {
            float4 b0 = *(const float4*)(B + (size_t)(kt + 2 * bkw)     * Nn + n0 + bn4 * 4);
            float4 b1 = *(const float4*)(B + (size_t)(kt + 2 * bkw + 1) * Nn + n0 + bn4 * 4);
            uint4 pkt;
            pkt.x = packh2(b0.x, b1.x); pkt.y = packh2(b0.y, b1.y);
            pkt.z = packh2(b0.z, b1.z); pkt.w = packh2(b0.w, b1.w);
            *(uint4*)&Bsw[bkw * 72 + bn4 * 4] = pkt;
        }
        __syncthreads();
        #pragma unroll
        for (int c = 0; c < 2; c++) {
            int kw0 = c * 8;
            uint32_t a[4] = {As16[(wm + g) * 20 + kw0 + t],     As16[(wm + g + 8) * 20 + kw0 + t],
                             As16[(wm + g) * 20 + kw0 + t + 4], As16[(wm + g + 8) * 20 + kw0 + t + 4]};
            #pragma unroll
            for (int nt = 0; nt < 4; nt++) {
                uint32_t b[2] = {Bsw[(kw0 + t) * 72 + wn + nt * 8 + g],
                                 Bsw[(kw0 + t + 4) * 72 + wn + nt * 8 + g]};
                mma_f16(acc[nt], a, b);
            }
        }
    }
    #pragma unroll
    for (int nt = 0; nt < 4; nt++) {
        int col = n0 + wn + nt * 8 + t * 2;
        #pragma unroll
        for (int half = 0; half < 2; half++) {
            int row = m0 + wm + g + half * 8;
            float v0 = sigm(acc[nt][half * 2 + 0] + bias[col]);
            float v1 = sigm(acc[nt][half * 2 + 1] + bias[col + 1]);
            C[(size_t)row * Nn + col]     = v0;
            C[(size_t)row * Nn + col + 1] = v1;
        }
    }
}

// --- pairbias pool: fp16 mma (K=16) + work stealing ---
__device__ __noinline__ void pairbias_pool(uint32_t* shm,
                                           const float* __restrict__ pair,
                                           const float* __restrict__ beta,
                                           const float* __restrict__ w,
                                           const float* __restrict__ b,
                                           const float* __restrict__ Wb,
                                           float* __restrict__ bias) {
    uint32_t* As16 = shm;               // [64 rows][68 words]
    uint32_t* Bsw  = shm + 64 * 68;     // [64 kwords][24]
    __shared__ unsigned int s_tile;

    int tid = threadIdx.x, lane = tid & 31, warp = tid >> 5;
    int r  = tid >> 2;
    int pq = tid & 3;
    int g = lane >> 2, t = lane & 3;
    int wm = (warp & 3) * 16;
    int hh = (warp >> 2) * 8;
    const unsigned int NT = NN / 64;

    __syncthreads();
    for (int i = tid; i < 64 * H_; i += 256) {
        int kw = i >> 4, h = i & 15;
        Bsw[kw * 24 + h] = packh2(__ldg(Wb + (2 * kw) * H_ + h),
                                  __ldg(Wb + (2 * kw + 1) * H_ + h));
    }

    for (;;) {
        if (tid == 0) s_tile = atomicAdd(&d_pbctr, 1u);
        __syncthreads();
        unsigned int tile = s_tile;
        if (tile >= NT) break;

        const float* row = pair + ((size_t)tile * 64 + r) * P_;
        float4 u[4][2];
        #pragma unroll
        for (int j = 0; j < 4; j++) {
            u[j][0] = *(const float4*)(row + 8 * pq + 32 * j);
            u[j][1] = *(const float4*)(row + 8 * pq + 32 * j + 4);
        }
        int p0 = tile * 64;
        float be0 = __ldg(beta + p0 + wm + g);
        float be1 = __ldg(beta + p0 + wm + g + 8);

        float s = 0.f, s2 = 0.f;
        #pragma unroll
        for (int j = 0; j < 4; j++)
            #pragma unroll
            for (int h2 = 0; h2 < 2; h2++) {
                const float4 f = u[j][h2];
                s  += f.x + f.y + f.z + f.w;
                s2 += f.x * f.x + f.y * f.y + f.z * f.z + f.w * f.w;
            }
        s  += __shfl_xor_sync(0xffffffffu, s, 1);  s  += __shfl_xor_sync(0xffffffffu, s, 2);
        s2 += __shfl_xor_sync(0xffffffffu, s2, 1); s2 += __shfl_xor_sync(0xffffffffu, s2, 2);
        float mean = s * (1.f / P_);
        float var  = s2 * (1.f / P_) - mean * mean;
        float rs   = rsqrtf(var + 1e-5f);

        #pragma unroll
        for (int j = 0; j < 4; j++) {
            int c0 = 8 * pq + 32 * j;
            const float4 wv0 = *(const float4*)(w + c0);
            const float4 bv0 = *(const float4*)(b + c0);
            const float4 wv1 = *(const float4*)(w + c0 + 4);
            const float4 bv1 = *(const float4*)(b + c0 + 4);
            const float4 f0 = u[j][0];
            const float4 f1 = u[j][1];
            float v0 = (f0.x - mean) * rs * wv0.x + bv0.x;
            float v1 = (f0.y - mean) * rs * wv0.y + bv0.y;
            float v2 = (f0.z - mean) * rs * wv0.z + bv0.z;
            float v3 = (f0.w - mean) * rs * wv0.w + bv0.w;
            float v4 = (f1.x - mean) * rs * wv1.x + bv1.x;
            float v5 = (f1.y - mean) * rs * wv1.y + bv1.y;
            float v6 = (f1.z - mean) * rs * wv1.z + bv1.z;
            float v7 = (f1.w - mean) * rs * wv1.w + bv1.w;
            uint4 pkt;
            pkt.x = packh2(v0, v1); pkt.y = packh2(v2, v3);
            pkt.z = packh2(v4, v5); pkt.w = packh2(v6, v7);
            *(uint4*)&As16[r * 68 + 4 * pq + 16 * j] = pkt;
        }
        __syncthreads();

        float acc[4] = {0.f, 0.f, 0.f, 0.f};
        #pragma unroll
        for (int c = 0; c < 8; c++) {
            int kw = c * 8;
            uint32_t a[4] = {As16[(wm + g) * 68 + kw + t],     As16[(wm + g + 8) * 68 + kw + t],
                             As16[(wm + g) * 68 + kw + t + 4], As16[(wm + g + 8) * 68 + kw + t + 4]};
            uint32_t bb[2] = {Bsw[(kw + t) * 24 + hh + g], Bsw[(kw + t + 4) * 24 + hh + g]};
            mma_f16(acc, a, bb);
        }

        int pr0 = p0 + wm + g, pr1 = pr0 + 8;
        int h0 = hh + 2 * t;
        bias[(size_t)(h0)     * NN + pr0] = acc[0] + be0;
        bias[(size_t)(h0 + 1) * NN + pr0] = acc[1] + be0;
        bias[(size_t)(h0)     * NN + pr1] = acc[2] + be1;
        bias[(size_t)(h0 + 1) * NN + pr1] = acc[3] + be1;
    }
}

#define FUSED_SMEM ((64*68 + 64*24)*4)
#define FUSED_GRID 592

__global__ __launch_bounds__(256, 4) void fused_mid(
    const float* __restrict__ A2,
    const float* __restrict__ Wq, const float* __restrict__ bq,
    const float* __restrict__ Wk, const float* __restrict__ Wv,
    const float* __restrict__ Wg,
    float* __restrict__ oq, float* __restrict__ ok,
    float* __restrict__ ov, float* __restrict__ og,
    const float* __restrict__ sIn, const float* __restrict__ Wout,
    const float* __restrict__ bout, float* __restrict__ gate,
    const float* __restrict__ pair, const float* __restrict__ beta,
    const float* __restrict__ lnpw, const float* __restrict__ lnpb,
    const float* __restrict__ Wb, float* __restrict__ bias) {
    extern __shared__ __align__(16) uint32_t shm[];
    int bx = blockIdx.x;
    if (bx < 144) {
        qkvg2_body(shm, bx % 12, bx / 12, 0, A2, bq, Wq, Wk, oq, ok);
    } else if (bx < 288) {
        int i = bx - 144;
        qkvg2_body(shm, i % 12, i / 12, 1, A2, bq, Wv, Wg, ov, og);
    } else if (bx < 432) {
        int i = bx - 288;
        gate_body(shm, i % 12, i / 12, sIn, Wout, bout, gate);
    }
    pairbias_pool(shm, pair, beta, lnpw, lnpb, Wb, bias);
}

// ---------------- flash attention, split-KV x2, fp16 mma ----------------
// AQ16 [64][28] (bank 28g+t bij.), Kw [24][72] (8(t+nt)+g bij.),
// Vw [32][56] (24t+8dt+g bij.), AP16 [64][36] (4g+t bij.)
#define ATTN_SMEM ((64*28 + 24*72 + 32*56 + 64*36)*4)

__global__ __launch_bounds__(128) void attn_f16(const float* __restrict__ q,
                                                const float* __restrict__ k,
                                                const float* __restrict__ v,
                                                const float* __restrict__ bias,
                                                float* __restrict__ opart,
                                                float2* __restrict__ mlv) {
    extern __shared__ uint32_t sm[];
    uint32_t* AQ16 = sm;                 // [64][28]
    uint32_t* Kw   = AQ16 + 64 * 28;     // [24 kwords][72]
    uint32_t* Vw   = Kw + 24 * 72;       // [32 kwords][56]
    uint32_t* AP16 = Vw + 32 * 56;       // [64][36]

    int h  = blockIdx.y;
    int q0 = blockIdx.x * 64;
    int sidx = blockIdx.z;
    int s0 = sidx * (N_ / 2);
    int tid = threadIdx.x, lane = tid & 31, warp = tid >> 5;
    int g = lane >> 2, t = lane & 3;
    int wm = warp * 16;

    // load Q tile (64 x 48) packed fp16
    #pragma unroll
    for (int it = 0; it < 6; it++) {
        int idx = tid + it * 128;
        int r = idx / 12, c4 = idx % 12;
        float4 v4 = *(const float4*)(q + (size_t)(q0 + r) * A_ + h * D_ + c4 * 4);
        uint2 wo; wo.x = packh2(v4.x, v4.y); wo.y = packh2(v4.z, v4.w);
        *(uint2*)&AQ16[r * 28 + c4 * 2] = wo;
    }

    float m0 = -1e30f, m1 = -1e30f, l0 = 0.f, l1 = 0.f;
    float oacc[6][4];
    #pragma unroll
    for (int dt = 0; dt < 6; dt++)
        #pragma unroll
        for (int e = 0; e < 4; e++) oacc[dt][e] = 0.f;

    const float scale = 0.144337567f;

    for (int j0 = s0; j0 < s0 + N_ / 2; j0 += 64) {
        __syncthreads();

        // bias prefetch (fp32, overlaps K/V load + QK mma)
        const float* bp0 = bias + (size_t)h * NN + (size_t)(q0 + wm + g) * N_ + j0;
        const float* bp1 = bp0 + 8 * N_;
        float2 bpre0[8], bpre1[8];
        #pragma unroll
        for (int nt = 0; nt < 8; nt++) {
            bpre0[nt] = *(const float2*)(bp0 + nt * 8 + 2 * t);
            bpre1[nt] = *(const float2*)(bp1 + nt * 8 + 2 * t);
        }

        // K: pack along head-dim (same row -> adjacent dims), column = key
        #pragma unroll
        for (int it = 0; it < 6; it++) {
            int idx = tid + it * 128;
            int r = idx / 12, j = idx % 12;
            float4 kv = *(const float4*)(k + (size_t)(j0 + r) * A_ + h * D_ + j * 4);
            Kw[(2 * j)     * 72 + r] = packh2(kv.x, kv.y);
            Kw[(2 * j + 1) * 72 + r] = packh2(kv.z, kv.w);
        }
        // V: pack key-pairs, column = dim
        #pragma unroll
        for (int it = 0; it < 3; it++) {
            int idx = tid + it * 128;
            int kw = idx / 12, dg = idx % 12;
            float4 v0 = *(const float4*)(v + (size_t)(j0 + 2 * kw)     * A_ + h * D_ + dg * 4);
            float4 v1 = *(const float4*)(v + (size_t)(j0 + 2 * kw + 1) * A_ + h * D_ + dg * 4);
            uint4 pkt;
            pkt.x = packh2(v0.x, v1.x); pkt.y = packh2(v0.y, v1.y);
            pkt.z = packh2(v0.z, v1.z); pkt.w = packh2(v0.w, v1.w);
            *(uint4*)&Vw[kw * 56 + dg * 4] = pkt;
        }
        __syncthreads();

        // S = Q K^T (3 chunks of K=16 over 48 dims)
        float sacc[8][4];
        #pragma unroll
        for (int nt = 0; nt < 8; nt++)
            #pragma unroll
            for (int e = 0; e < 4; e++) sacc[nt][e] = 0.f;

        #pragma unroll
        for (int c = 0; c < 3; c++) {
            int kw0 = c * 8;
            uint32_t a[4] = {AQ16[(wm + g) * 28 + kw0 + t],     AQ16[(wm + g + 8) * 28 + kw0 + t],
                             AQ16[(wm + g) * 28 + kw0 + t + 4], AQ16[(wm + g + 8) * 28 + kw0 + t + 4]};
            #pragma unroll
            for (int nt = 0; nt < 8; nt++) {
                uint32_t b[2] = {Kw[(kw0 + t) * 72 + nt * 8 + g],
                                 Kw[(kw0 + t + 4) * 72 + nt * 8 + g]};
                mma_f16(sacc[nt], a, b);
            }
        }

        #pragma unroll
        for (int nt = 0; nt < 8; nt++) {
            sacc[nt][0] = sacc[nt][0] * scale + bpre0[nt].x;
            sacc[nt][1] = sacc[nt][1] * scale + bpre0[nt].y;
            sacc[nt][2] = sacc[nt][2] * scale + bpre1[nt].x;
            sacc[nt][3] = sacc[nt][3] * scale + bpre1[nt].y;
        }

        // online softmax (quad-local)
        float mx0 = -1e30f, mx1 = -1e30f;
        #pragma unroll
        for (int nt = 0; nt < 8; nt++) {
            mx0 = fmaxf(mx0, fmaxf(sacc[nt][0], sacc[nt][1]));
            mx1 = fmaxf(mx1, fmaxf(sacc[nt][2], sacc[nt][3]));
        }
        mx0 = fmaxf(mx0, __shfl_xor_sync(0xffffffffu, mx0, 1));
        mx0 = fmaxf(mx0, __shfl_xor_sync(0xffffffffu, mx0, 2));
        mx1 = fmaxf(mx1, __shfl_xor_sync(0xffffffffu, mx1, 1));
        mx1 = fmaxf(mx1, __shfl_xor_sync(0xffffffffu, mx1, 2));
        float mn0 = fmaxf(m0, mx0), mn1 = fmaxf(m1, mx1);
        float cr0 = __expf(m0 - mn0), cr1 = __expf(m1 - mn1);
        m0 = mn0; m1 = mn1;

        float s0r = 0.f, s1r = 0.f;
        #pragma unroll
        for (int nt = 0; nt < 8; nt++) {
            float p00 = __expf(sacc[nt][0] - mn0);
            float p01 = __expf(sacc[nt][1] - mn0);
            float p10 = __expf(sacc[nt][2] - mn1);
            float p11 = __expf(sacc[nt][3] - mn1);
            s0r += p00 + p01; s1r += p10 + p11;
            AP16[(wm + g)     * 36 + nt * 4 + t] = packh2(p00, p01);
            AP16[(wm + g + 8) * 36 + nt * 4 + t] = packh2(p10, p11);
        }
        s0r += __shfl_xor_sync(0xffffffffu, s0r, 1);
        s0r += __shfl_xor_sync(0xffffffffu, s0r, 2);
        s1r += __shfl_xor_sync(0xffffffffu, s1r, 1);
        s1r += __shfl_xor_sync(0xffffffffu, s1r, 2);
        l0 = l0 * cr0 + s0r;
        l1 = l1 * cr1 + s1r;

        #pragma unroll
        for (int dt = 0; dt < 6; dt++) {
            oacc[dt][0] *= cr0; oacc[dt][1] *= cr0;
            oacc[dt][2] *= cr1; oacc[dt][3] *= cr1;
        }
        __syncwarp();

        // O += P V (4 chunks of K=16 over 64 keys)
        #pragma unroll
        for (int c = 0; c < 4; c++) {
            int kw0 = c * 8;
            uint32_t a[4] = {AP16[(wm + g) * 36 + kw0 + t],     AP16[(wm + g + 8) * 36 + kw0 + t],
                             AP16[(wm + g) * 36 + kw0 + t + 4], AP16[(wm + g + 8) * 36 + kw0 + t + 4]};
            #pragma unroll
            for (int dt = 0; dt < 6; dt++) {
                uint32_t b[2] = {Vw[(kw0 + t) * 56 + dt * 8 + g],
                                 Vw[(kw0 + t + 4) * 56 + dt * 8 + g]};
                mma_f16(oacc[dt], a, b);
            }
        }
    }

    float* op = opart + (size_t)sidx * N_ * A_;
    int r0 = q0 + wm + g, r1 = r0 + 8;
    #pragma unroll
    for (int dt = 0; dt < 6; dt++) {
        int d = dt * 8 + 2 * t;
        size_t i00 = (size_t)r0 * A_ + h * D_ + d;
        size_t i10 = (size_t)r1 * A_ + h * D_ + d;
        op[i00]     = oacc[dt][0];
        op[i00 + 1] = oacc[dt][1];
        op[i10]     = oacc[dt][2];
        op[i10 + 1] = oacc[dt][3];
    }
    if (t == 0) {
        mlv[(size_t)sidx * H_ * N_ + h * N_ + r0] = make_float2(m0, l0);
        mlv[(size_t)sidx * H_ * N_ + h * N_ + r1] = make_float2(m1, l1);
    }
}

// ---------------- merge split-KV partials + gate ----------------
__global__ __launch_bounds__(256) void attn_merge(const float* __restrict__ op,
                                                  const float2* __restrict__ ml,
                                                  const float* __restrict__ gt,
                                                  float* __restrict__ o) {
    int idx = blockIdx.x * 256 + threadIdx.x;
    int n  = idx / 192;
    int c4 = idx - n * 192;
    int h  = c4 / 12;
    float2 ml1 = ml[h * N_ + n];
    float2 ml2 = ml[H_ * N_ + h * N_ + n];
    float m  = fmaxf(ml1.x, ml2.x);
    float w1 = __expf(ml1.x - m), w2 = __expf(ml2.x - m);
    float inv = 1.f / (w1 * ml1.y + w2 * ml2.y);
    size_t off = (size_t)n * A_ + c4 * 4;
    const float4 a1 = *(const float4*)(op + off);
    const float4 a2 = *(const float4*)(op + (size_t)N_ * A_ + off);
    const float4 g4 = *(const float4*)(gt + off);
    float4 r;
    r.x = (w1 * a1.x + w2 * a2.x) * inv * g4.x;
    r.y = (w1 * a1.y + w2 * a2.y) * inv * g4.y;
    r.z = (w1 * a1.z + w2 * a2.z) * inv * g4.z;
    r.w = (w1 * a1.w + w2 * a2.w) * inv * g4.w;
    *(float4*)(o + off) = r;
}

// ---------------- launch ----------------
extern "C" void kernel_launch(void* const* d_in, const int* in_sizes, int n_in,
                              void* d_out, int out_size) {
    const float* a       = (const float*)d_in[0];
    const float* s       = (const float*)d_in[1];
    const float* pair    = (const float*)d_in[2];
    const float* beta    = (const float*)d_in[3];
    const float* ln_s_w  = (const float*)d_in[4];
    const float* gamma_w = (const float*)d_in[5];
    const float* gamma_b = (const float*)d_in[6];
    const float* shift_w = (const float*)d_in[7];
    const float* Wq      = (const float*)d_in[8];
    const float* bq      = (const float*)d_in[9];
    const float* Wk      = (const float*)d_in[10];
    const float* Wv      = (const float*)d_in[11];
    const float* ln_p_w  = (const float*)d_in[12];
    const float* ln_p_b  = (const float*)d_in[13];
    const float* Wb      = (const float*)d_in[14];
    const float* Wg      = (const float*)d_in[15];
    const float* Wp      = (const float*)d_in[16];
    const float* Wout    = (const float*)d_in[17];
    const float* bout    = (const float*)d_in[18];
    float* out = (float*)d_out;

    float *p_sn, *p_an, *p_a2, *p_q, *p_k, *p_v, *p_gt, *p_bias, *p_o, *p_gate, *p_opart;
    float2 *p_ml;
    cudaGetSymbolAddress((void**)&p_sn,    d_sn);
    cudaGetSymbolAddress((void**)&p_an,    d_an);
    cudaGetSymbolAddress((void**)&p_a2,    d_a2);
    cudaGetSymbolAddress((void**)&p_q,     d_q);
    cudaGetSymbolAddress((void**)&p_k,     d_k);
    cudaGetSymbolAddress((void**)&p_v,     d_v);
    cudaGetSymbolAddress((void**)&p_gt,    d_gt);
    cudaGetSymbolAddress((void**)&p_bias,  d_bias);
    cudaGetSymbolAddress((void**)&p_o,     d_o);
    cudaGetSymbolAddress((void**)&p_gate,  d_gate);
    cudaGetSymbolAddress((void**)&p_opart, d_opart);
    cudaGetSymbolAddress((void**)&p_ml,    d_ml);

    cudaFuncSetAttribute(attn_f16,   cudaFuncAttributeMaxDynamicSharedMemorySize, ATTN_SMEM);
    cudaFuncSetAttribute(fused_mid,  cudaFuncAttributeMaxDynamicSharedMemorySize, FUSED_SMEM);

    dim3 g2(A_ / 64, N_ / 64);

    ln2_kernel<<<dim3(N_, 2), 256>>>(s, ln_s_w, p_sn, a, p_an);
    adaln_f16<<<g2, 256>>>(p_sn, gamma_w, gamma_b, shift_w, p_an, p_a2);
    fused_mid<<<FUSED_GRID, 256, FUSED_SMEM>>>(
        p_a2, Wq, bq, Wk, Wv, Wg, p_q, p_k, p_v, p_gt,
        s, Wout, bout, p_gate,
        pair, beta, ln_p_w, ln_p_b, Wb, p_bias);
    dim3 ga(N_ / 64, H_, 2);
    attn_f16<<<ga, 128, ATTN_SMEM>>>(p_q, p_k, p_v, p_bias, p_opart, p_ml);
    attn_merge<<<576, 256>>>(p_opart, p_ml, p_gt, p_o);
    gemm_f16<<<g2, 256>>>(p_o, Wp, out, A_, A_, p_gate);
}